// round 2
// baseline (speedup 1.0000x reference)
#include <cuda_runtime.h>
#include <math.h>

#define BB    4
#define NN    16384
#define CC    384
#define HEADS 8
#define HD    48
#define ROWS  (BB*NN)      // 65536
#define BH    (BB*HEADS)   // 32
#define FF    96           // feature dim (pos+neg)
#define INV_N (1.0f/16384.0f)

// ---------------- scratch (static device globals; no allocation) ----------------
__device__ float g_q[ROWS*CC];      // q/scale ; later reused as "pre" buffer
__device__ float g_g[ROWS*CC];
__device__ float g_k[ROWS*CC];      // (k+pos)/scale
__device__ float g_v[ROWS*CC];
__device__ float g_attn[ROWS*CC];
__device__ float g_KV[BH*FF*HD];    // sum over n of kk[n,u]*v[n,e]
__device__ float g_km[BH*FF];       // sum over n of kk[n,u]
__device__ float g_scale[CC];       // softplus(scale_p)
__device__ float g_power[CC];       // 1 + 4*sigmoid(power_p)

// ---------------- prep: per-channel scale & power ----------------
__global__ void prep_kernel(const float* __restrict__ scale_p,
                            const float* __restrict__ power_p) {
    int c = threadIdx.x;
    if (c < CC) {
        g_scale[c] = log1pf(expf(scale_p[c]));
        g_power[c] = 1.0f + 4.0f / (1.0f + expf(-power_p[c]));
    }
}

__global__ void zero_kv_kernel() {
    int i = blockIdx.x * blockDim.x + threadIdx.x;
    if (i < BH*FF*HD) g_KV[i] = 0.0f;
    if (i < BH*FF)    g_km[i] = 0.0f;
}

// ---------------- SGEMM 128x128x8, 256 threads, 8x8 per thread ----------------
// MODE 0: qg   -> q (scaled) / g           (A = x, B = W_qg, Ncols=768)
// MODE 1: kv   -> k (+pos, scaled) / v     (A = x, B = W_kv, Ncols=768, aux=pos_enc)
// MODE 2: proj -> out = pre@W_proj + bias  (A = g_q(pre), B = W_proj, Ncols=384, aux=b_proj)
template<int MODE>
__global__ void __launch_bounds__(256)
sgemm_kernel(const float* __restrict__ A, const float* __restrict__ Bm,
             const float* __restrict__ aux, float* __restrict__ out, int Ncols) {
    __shared__ __align__(16) float sA[8][128];
    __shared__ __align__(16) float sB[8][128];

    const float* Ap = (MODE == 2) ? (const float*)g_q : A;

    int tid  = threadIdx.x;
    int row0 = blockIdx.y * 128;
    int col0 = blockIdx.x * 128;
    int ty   = tid >> 4;       // 0..15
    int tx   = tid & 15;       // 0..15

    float acc[8][8];
#pragma unroll
    for (int i = 0; i < 8; i++)
#pragma unroll
        for (int j = 0; j < 8; j++) acc[i][j] = 0.0f;

    const int K = CC;
    int ar = tid >> 1;            // 0..127
    int ac = (tid & 1) * 4;       // 0 or 4
    int br = tid >> 5;            // 0..7
    int bc = (tid & 31) * 4;      // 0..124

    for (int k0 = 0; k0 < K; k0 += 8) {
        float4 av = *(const float4*)&Ap[(size_t)(row0 + ar) * K + k0 + ac];
        sA[ac + 0][ar] = av.x; sA[ac + 1][ar] = av.y;
        sA[ac + 2][ar] = av.z; sA[ac + 3][ar] = av.w;
        float4 bv = *(const float4*)&Bm[(size_t)(k0 + br) * Ncols + col0 + bc];
        *(float4*)&sB[br][bc] = bv;
        __syncthreads();

#pragma unroll
        for (int kk = 0; kk < 8; kk++) {
            float a[8], b[8];
            *(float4*)(a)     = *(float4*)&sA[kk][ty * 8];
            *(float4*)(a + 4) = *(float4*)&sA[kk][ty * 8 + 4];
            *(float4*)(b)     = *(float4*)&sB[kk][tx * 8];
            *(float4*)(b + 4) = *(float4*)&sB[kk][tx * 8 + 4];
#pragma unroll
            for (int i = 0; i < 8; i++)
#pragma unroll
                for (int j = 0; j < 8; j++)
                    acc[i][j] = fmaf(a[i], b[j], acc[i][j]);
        }
        __syncthreads();
    }

#pragma unroll
    for (int i = 0; i < 8; i++) {
        int r = row0 + ty * 8 + i;
#pragma unroll
        for (int j = 0; j < 8; j++) {
            int cidx = col0 + tx * 8 + j;
            float v = acc[i][j];
            if (MODE == 0) {
                if (cidx < CC) g_q[(size_t)r * CC + cidx] = v / g_scale[cidx];
                else           g_g[(size_t)r * CC + (cidx - CC)] = v;
            } else if (MODE == 1) {
                if (cidx < CC) {
                    int n = r & (NN - 1);
                    g_k[(size_t)r * CC + cidx] =
                        (v + aux[(size_t)n * CC + cidx]) / g_scale[cidx];
                } else {
                    g_v[(size_t)r * CC + (cidx - CC)] = v;
                }
            } else {
                out[(size_t)r * Ncols + cidx] = v + aux[cidx];
            }
        }
    }
}

// ---------------- reduction: KV[bh][u][e] and km[bh][u] ----------------
// grid (BH, 32 chunks of 512 tokens), 256 threads
__global__ void __launch_bounds__(256) reduce_kv_kernel() {
    int bh = blockIdx.x;
    int b = bh >> 3, h = bh & 7;
    int chunk = blockIdx.y;
    int t = threadIdx.x;

    __shared__ float s_k[16][48];
    __shared__ float s_v[16][48];
    __shared__ float s_kk[16][96];

    float acc[6][3];
#pragma unroll
    for (int i = 0; i < 6; i++)
#pragma unroll
        for (int j = 0; j < 3; j++) acc[i][j] = 0.0f;
    float kmacc[6] = {0, 0, 0, 0, 0, 0};

    int tokb = t & 15;
    float pw[6];
#pragma unroll
    for (int j = 0; j < 6; j++) {
        int u = (t >> 4) + 16 * j;
        int d = (u < 48) ? u : (u - 48);
        pw[j] = g_power[h * 48 + d];
    }

    size_t base = ((size_t)(b * NN) + (size_t)chunk * 512) * CC + h * 48;

    for (int batch = 0; batch < 32; batch++) {
        for (int e = t; e < 16 * 48; e += 256) {
            int tok = e / 48, d = e % 48;
            size_t gi = base + (size_t)(batch * 16 + tok) * CC + d;
            s_k[tok][d] = g_k[gi];
            s_v[tok][d] = g_v[gi];
        }
        __syncthreads();

#pragma unroll
        for (int j = 0; j < 6; j++) {
            int u = (t >> 4) + 16 * j;
            int d = (u < 48) ? u : (u - 48);
            float kv = s_k[tokb][d];
            float r = (u < 48) ? kv : -kv;
            float val = (r > 0.0f) ? __powf(r, pw[j]) : 0.0f;
            s_kk[tokb][u] = val;
            kmacc[j] += val;
        }
        __syncthreads();

        int u0 = (t >> 4) * 6, e0 = (t & 15) * 3;
#pragma unroll 4
        for (int tok = 0; tok < 16; tok++) {
            float v0 = s_v[tok][e0], v1 = s_v[tok][e0 + 1], v2 = s_v[tok][e0 + 2];
#pragma unroll
            for (int i = 0; i < 6; i++) {
                float ku = s_kk[tok][u0 + i];
                acc[i][0] = fmaf(ku, v0, acc[i][0]);
                acc[i][1] = fmaf(ku, v1, acc[i][1]);
                acc[i][2] = fmaf(ku, v2, acc[i][2]);
            }
        }
        __syncthreads();
    }

    int u0 = (t >> 4) * 6, e0 = (t & 15) * 3;
#pragma unroll
    for (int i = 0; i < 6; i++)
#pragma unroll
        for (int j = 0; j < 3; j++)
            atomicAdd(&g_KV[((size_t)bh * FF + u0 + i) * HD + e0 + j], acc[i][j]);
#pragma unroll
    for (int j = 0; j < 6; j++)
        atomicAdd(&g_km[(size_t)bh * FF + (t >> 4) + 16 * j], kmacc[j]);
}

// ---------------- per-token attention: qs features + z + 96x48 matvec ----------------
// grid (NN/64, BH), 256 threads; 64 tokens per block
__global__ void __launch_bounds__(256) attn_kernel() {
    int bh = blockIdx.y;
    int b = bh >> 3, h = bh & 7;
    int n0 = blockIdx.x * 64;
    int t = threadIdx.x;

    __shared__ float s_qs[64][97];
    __shared__ float s_M[96][48];
    __shared__ float s_km[96];
    __shared__ float s_z[64][2];

    float (*s_qraw)[48] = (float(*)[48])&s_M[0][0];   // 64*48 floats fit in 96*48

    size_t base = ((size_t)(b * NN) + n0) * CC + h * 48;

    // phase 1: load raw q tile + km
    for (int e = t; e < 64 * 48; e += 256) {
        int tok = e / 48, d = e % 48;
        s_qraw[tok][d] = g_q[base + (size_t)tok * CC + d];
    }
    if (t < 96) s_km[t] = g_km[(size_t)bh * FF + t] * INV_N;
    __syncthreads();

    // phase 2: qs features
    for (int idx = t; idx < 64 * 96; idx += 256) {
        int tok = idx / 96, u = idx % 96;
        int d = (u < 48) ? u : (u - 48);
        float qv = s_qraw[tok][d];
        float r = (u < 48) ? qv : -qv;
        float p = g_power[h * 48 + d];
        s_qs[tok][u] = (r > 0.0f) ? __powf(r, p) : 0.0f;
    }
    __syncthreads();

    // phase 3: z per token (reads s_qs/s_km) + load M (overwrites s_qraw region)
    if (t < 64) {
        float zs = 0.0f, zo = 0.0f;
#pragma unroll
        for (int u = 0; u < 96; u++) {
            float qv = s_qs[t][u];
            zs = fmaf(qv, s_km[u], zs);
            zo = fmaf(qv, s_km[(u + 48) % 96], zo);
        }
        s_z[t][0] = 1.0f / (zs + 1e-6f);
        s_z[t][1] = 1.0f / (zo + 1e-6f);
    }
    for (int idx = t; idx < 96 * 48; idx += 256) {
        int u = idx / 48, e = idx % 48;
        float val = (e < 24) ? g_KV[((size_t)bh * FF + u) * HD + e]
                             : g_KV[((size_t)bh * FF + ((u + 48) % 96)) * HD + e];
        s_M[u][e] = val * INV_N;
    }
    __syncthreads();

    // phase 4: 64x48 = qs(64x96) @ M(96x48), 4 tokens x 3 cols per thread
    int tg = t >> 4, eg = t & 15;
    int tok0 = tg * 4, e0 = eg * 3;
    float acc[4][3];
#pragma unroll
    for (int i = 0; i < 4; i++)
#pragma unroll
        for (int j = 0; j < 3; j++) acc[i][j] = 0.0f;

#pragma unroll 8
    for (int k = 0; k < 96; k++) {
        float a0 = s_qs[tok0][k], a1 = s_qs[tok0 + 1][k];
        float a2 = s_qs[tok0 + 2][k], a3 = s_qs[tok0 + 3][k];
        float b0 = s_M[k][e0], b1 = s_M[k][e0 + 1], b2 = s_M[k][e0 + 2];
        acc[0][0] = fmaf(a0, b0, acc[0][0]); acc[0][1] = fmaf(a0, b1, acc[0][1]); acc[0][2] = fmaf(a0, b2, acc[0][2]);
        acc[1][0] = fmaf(a1, b0, acc[1][0]); acc[1][1] = fmaf(a1, b1, acc[1][1]); acc[1][2] = fmaf(a1, b2, acc[1][2]);
        acc[2][0] = fmaf(a2, b0, acc[2][0]); acc[2][1] = fmaf(a2, b1, acc[2][1]); acc[2][2] = fmaf(a2, b2, acc[2][2]);
        acc[3][0] = fmaf(a3, b0, acc[3][0]); acc[3][1] = fmaf(a3, b1, acc[3][1]); acc[3][2] = fmaf(a3, b2, acc[3][2]);
    }

#pragma unroll
    for (int i = 0; i < 4; i++) {
        int tok = tok0 + i;
#pragma unroll
        for (int j = 0; j < 3; j++) {
            int e = e0 + j;
            float z = s_z[tok][(e < 24) ? 0 : 1];
            g_attn[base + (size_t)tok * CC + e] = acc[i][j] * z;
        }
    }
}

// ---------------- depthwise 5x5 conv + combine: pre = (attn + conv(v) + bias)*g ----------------
__global__ void __launch_bounds__(256) conv_combine_kernel(const float* __restrict__ w,
                                                           const float* __restrict__ wb) {
    __shared__ float s_w[48 * 25];
    __shared__ float s_b[48];
    int t = threadIdx.x;
    for (int i = t; i < 48 * 25; i += 256) s_w[i] = w[i];
    if (t < 48) s_b[t] = wb[t];
    __syncthreads();

    int idx = blockIdx.x * 256 + t;            // < 25,165,824
    int c = idx % CC;
    int rown = idx / CC;                        // b*N + n
    int n = rown & (NN - 1);
    int b = rown >> 14;
    int d = c % 48;
    int y = n >> 7, x = n & 127;

    float accv = s_b[d];
#pragma unroll
    for (int dy = -2; dy <= 2; dy++) {
        int yy = y + dy;
        if ((unsigned)yy < 128u) {
#pragma unroll
            for (int dx = -2; dx <= 2; dx++) {
                int xx = x + dx;
                if ((unsigned)xx < 128u) {
                    accv = fmaf(g_v[((size_t)(b << 14) + (yy << 7) + xx) * CC + c],
                                s_w[d * 25 + (dy + 2) * 5 + (dx + 2)], accv);
                }
            }
        }
    }
    float pre = (g_attn[idx] + accv) * g_g[idx];
    g_q[idx] = pre;   // reuse g_q as "pre" buffer
}

// ---------------- launch ----------------
extern "C" void kernel_launch(void* const* d_in, const int* in_sizes, int n_in,
                              void* d_out, int out_size) {
    const float* x       = (const float*)d_in[0];
    const float* W_qg    = (const float*)d_in[1];
    const float* W_kv    = (const float*)d_in[2];
    const float* W_proj  = (const float*)d_in[3];
    const float* b_proj  = (const float*)d_in[4];
    const float* pos_enc = (const float*)d_in[5];
    const float* power_p = (const float*)d_in[6];
    const float* scale_p = (const float*)d_in[7];
    const float* dwc_w   = (const float*)d_in[8];
    const float* dwc_b   = (const float*)d_in[9];
    float* out = (float*)d_out;

    prep_kernel<<<1, 384>>>(scale_p, power_p);
    zero_kv_kernel<<<(BH * FF * HD + 255) / 256, 256>>>();

    dim3 g_qg(768 / 128, ROWS / 128);
    sgemm_kernel<0><<<g_qg, 256>>>(x, W_qg, nullptr, nullptr, 768);

    dim3 g_kv(768 / 128, ROWS / 128);
    sgemm_kernel<1><<<g_kv, 256>>>(x, W_kv, pos_enc, nullptr, 768);

    dim3 g_red(BH, 32);
    reduce_kv_kernel<<<g_red, 256>>>();

    dim3 g_attn_grid(NN / 64, BH);
    attn_kernel<<<g_attn_grid, 256>>>();

    conv_combine_kernel<<<(ROWS * CC) / 256, 256>>>(dwc_w, dwc_b);

    dim3 g_proj(384 / 128, ROWS / 128);
    sgemm_kernel<2><<<g_proj, 256>>>(nullptr, W_proj, b_proj, out, 384);
}

// round 3
// speedup vs baseline: 1.2622x; 1.2622x over previous
#include <cuda_runtime.h>
#include <math.h>
#include <stdint.h>

#define BB    4
#define NN    16384
#define CC    384
#define HEADS 8
#define HD    48
#define ROWS  (BB*NN)      // 65536
#define BH    (BB*HEADS)   // 32
#define FF    96           // feature dim (pos+neg)
#define INV_N (1.0f/16384.0f)

// ---------------- scratch (static device globals; no allocation) ----------------
__device__ float g_q[ROWS*CC];      // q/scale ; later reused as "pre" buffer
__device__ float g_g[ROWS*CC];
__device__ float g_k[ROWS*CC];      // (k+pos)/scale
__device__ float g_v[ROWS*CC];
__device__ float g_attn[ROWS*CC];
__device__ float g_KV[BH*FF*HD];    // sum over n of kk[n,u]*v[n,e]
__device__ float g_km[BH*FF];       // sum over n of kk[n,u]
__device__ float g_scale[CC];       // softplus(scale_p)
__device__ float g_power[CC];       // 1 + 4*sigmoid(power_p)

// ---------------- prep: per-channel scale & power ----------------
__global__ void prep_kernel(const float* __restrict__ scale_p,
                            const float* __restrict__ power_p) {
    int c = threadIdx.x;
    if (c < CC) {
        g_scale[c] = log1pf(expf(scale_p[c]));
        g_power[c] = 1.0f + 4.0f / (1.0f + expf(-power_p[c]));
    }
}

__global__ void zero_kv_kernel() {
    int i = blockIdx.x * blockDim.x + threadIdx.x;
    if (i < BH*FF*HD) g_KV[i] = 0.0f;
    if (i < BH*FF)    g_km[i] = 0.0f;
}

// ---------------- tf32 helpers ----------------
__device__ __forceinline__ unsigned f2tf(float f) {
    unsigned r;
    asm("cvt.rna.tf32.f32 %0, %1;" : "=r"(r) : "f"(f));
    return r;
}

__device__ __forceinline__ void mma_tf32(float d[4], const unsigned a[4], const unsigned b[2]) {
    asm volatile(
        "mma.sync.aligned.m16n8k8.row.col.f32.tf32.tf32.f32 "
        "{%0,%1,%2,%3}, {%4,%5,%6,%7}, {%8,%9}, {%0,%1,%2,%3};"
        : "+f"(d[0]), "+f"(d[1]), "+f"(d[2]), "+f"(d[3])
        : "r"(a[0]), "r"(a[1]), "r"(a[2]), "r"(a[3]), "r"(b[0]), "r"(b[1]));
}

// ---------------- tf32 tensor-core GEMM, 128x128 tile, BK=16, 256 threads ----------------
// MODE 0: qg   -> q (scaled) / g           (A = x, B = W_qg, Ncols=768)
// MODE 1: kv   -> k (+pos, scaled) / v     (A = x, B = W_kv, Ncols=768, aux=pos_enc)
// MODE 2: proj -> out = pre@W_proj + bias  (A = g_q(pre), B = W_proj, Ncols=384, aux=b_proj)
//
// smem holds tf32 values in FRAGMENT-MAJOR layout so the mainloop fetches each
// m16n8k8 fragment with one LDS.128 (A) / LDS.64 (B):
//   sA[buf][ ((s*8 + mi)*32 + lane)*4 + {a0,a1,a2,a3} ]   s = k-step (0..1), mi = m-tile (0..7)
//   sB[buf][ ((s*16 + ni)*32 + lane)*2 + {b0,b1} ]        ni = n-tile (0..15)
template<int MODE>
__global__ void __launch_bounds__(256)
tgemm_kernel(const float* __restrict__ A, const float* __restrict__ Bm,
             const float* __restrict__ aux, float* __restrict__ out, int Ncols) {
    __shared__ unsigned sA[2][2048];
    __shared__ unsigned sB[2][2048];

    const float* Ap = (MODE == 2) ? (const float*)g_q : A;

    const int tid  = threadIdx.x;
    const int lane = tid & 31;
    const int warp = tid >> 5;
    const int wm   = warp >> 2;     // 0..1  (64 rows each)
    const int wn   = warp & 3;      // 0..3  (32 cols each)
    const int row0 = blockIdx.y * 128;
    const int col0 = blockIdx.x * 128;
    const int K    = CC;

    float d[4][4][4];
#pragma unroll
    for (int i = 0; i < 4; i++)
#pragma unroll
        for (int j = 0; j < 4; j++)
#pragma unroll
            for (int f = 0; f < 4; f++) d[i][j][f] = 0.0f;

    // global-load coordinates
    const int ar  = tid >> 1;             // 0..127 (A row)
    const int ac0 = (tid & 1) * 8;        // A col base (2 float4)
    const int br  = tid >> 4;             // 0..15   (B k-row)
    const int bc0 = (tid & 15) * 8;       // B col base (2 float4)

    float4 ra[2], rb[2];

    // precomputed STS addresses
    const int a_mi = ar >> 4, a_rl = ar & 15;
    unsigned a_sts[2], b_sts[2];
#pragma unroll
    for (int h = 0; h < 2; h++) {
        int kc = ac0 + h * 4;
        int s = kc >> 3;
        int idx2 = ((kc >> 2) & 1) * 2 + (a_rl >= 8 ? 1 : 0);
        a_sts[h] = ((s * 8 + a_mi) * 32 + (a_rl & 7) * 4) * 4 + idx2;
    }
    {
        int s = br >> 3, kr = br & 7;
        int slot = (kr >= 4) ? 1 : 0;
#pragma unroll
        for (int h = 0; h < 2; h++) {
            int c0 = bc0 + h * 4;
            int ni = c0 >> 3, g0 = c0 & 7;
            b_sts[h] = ((s * 16 + ni) * 32 + g0 * 4 + (kr & 3)) * 2 + slot;
        }
    }

    const int nk = K / 16;

    // ---- prologue: load + store tile 0 ----
    {
        const float* ap = &Ap[(size_t)(row0 + ar) * K + ac0];
        ra[0] = *(const float4*)(ap);
        ra[1] = *(const float4*)(ap + 4);
        const float* bp = &Bm[(size_t)br * Ncols + col0 + bc0];
        rb[0] = *(const float4*)(bp);
        rb[1] = *(const float4*)(bp + 4);
#pragma unroll
        for (int h = 0; h < 2; h++) {
            sA[0][a_sts[h] + 0]  = f2tf(ra[h].x);
            sA[0][a_sts[h] + 4]  = f2tf(ra[h].y);
            sA[0][a_sts[h] + 8]  = f2tf(ra[h].z);
            sA[0][a_sts[h] + 12] = f2tf(ra[h].w);
            sB[0][b_sts[h] + 0]  = f2tf(rb[h].x);
            sB[0][b_sts[h] + 8]  = f2tf(rb[h].y);
            sB[0][b_sts[h] + 16] = f2tf(rb[h].z);
            sB[0][b_sts[h] + 24] = f2tf(rb[h].w);
        }
    }
    __syncthreads();

    for (int kb = 0; kb < nk; kb++) {
        const int buf = kb & 1;
        if (kb + 1 < nk) {
            int k0 = (kb + 1) * 16;
            const float* ap = &Ap[(size_t)(row0 + ar) * K + k0 + ac0];
            ra[0] = *(const float4*)(ap);
            ra[1] = *(const float4*)(ap + 4);
            const float* bp = &Bm[(size_t)(k0 + br) * Ncols + col0 + bc0];
            rb[0] = *(const float4*)(bp);
            rb[1] = *(const float4*)(bp + 4);
        }

        // ---- compute on buf ----
#pragma unroll
        for (int s = 0; s < 2; s++) {
            unsigned afr[4][4], bfr[4][2];
#pragma unroll
            for (int i = 0; i < 4; i++) {
                uint4 t = *(const uint4*)&sA[buf][((s * 8 + wm * 4 + i) * 32 + lane) * 4];
                afr[i][0] = t.x; afr[i][1] = t.y; afr[i][2] = t.z; afr[i][3] = t.w;
            }
#pragma unroll
            for (int j = 0; j < 4; j++) {
                uint2 t = *(const uint2*)&sB[buf][((s * 16 + wn * 4 + j) * 32 + lane) * 2];
                bfr[j][0] = t.x; bfr[j][1] = t.y;
            }
#pragma unroll
            for (int i = 0; i < 4; i++)
#pragma unroll
                for (int j = 0; j < 4; j++)
                    mma_tf32(d[i][j], afr[i], bfr[j]);
        }

        if (kb + 1 < nk) {
            const int nb = buf ^ 1;
#pragma unroll
            for (int h = 0; h < 2; h++) {
                sA[nb][a_sts[h] + 0]  = f2tf(ra[h].x);
                sA[nb][a_sts[h] + 4]  = f2tf(ra[h].y);
                sA[nb][a_sts[h] + 8]  = f2tf(ra[h].z);
                sA[nb][a_sts[h] + 12] = f2tf(ra[h].w);
                sB[nb][b_sts[h] + 0]  = f2tf(rb[h].x);
                sB[nb][b_sts[h] + 8]  = f2tf(rb[h].y);
                sB[nb][b_sts[h] + 16] = f2tf(rb[h].z);
                sB[nb][b_sts[h] + 24] = f2tf(rb[h].w);
            }
            __syncthreads();
        }
    }

    // ---- epilogue ----
    const int g  = lane >> 2;
    const int cq = (lane & 3) * 2;
#pragma unroll
    for (int i = 0; i < 4; i++) {
        int rbase = row0 + wm * 64 + i * 16 + g;
#pragma unroll
        for (int j = 0; j < 4; j++) {
            int cbase = col0 + wn * 32 + j * 8 + cq;
#pragma unroll
            for (int f = 0; f < 4; f++) {
                int r    = rbase + ((f >> 1) ? 8 : 0);
                int cidx = cbase + (f & 1);
                float v  = d[i][j][f];
                if (MODE == 0) {
                    if (cidx < CC) g_q[(size_t)r * CC + cidx] = v / g_scale[cidx];
                    else           g_g[(size_t)r * CC + (cidx - CC)] = v;
                } else if (MODE == 1) {
                    if (cidx < CC) {
                        int n = r & (NN - 1);
                        g_k[(size_t)r * CC + cidx] =
                            (v + aux[(size_t)n * CC + cidx]) / g_scale[cidx];
                    } else {
                        g_v[(size_t)r * CC + (cidx - CC)] = v;
                    }
                } else {
                    out[(size_t)r * Ncols + cidx] = v + aux[cidx];
                }
            }
        }
    }
}

// ---------------- reduction: KV[bh][u][e] and km[bh][u] ----------------
// grid (BH, 32 chunks of 512 tokens), 256 threads
__global__ void __launch_bounds__(256) reduce_kv_kernel() {
    int bh = blockIdx.x;
    int b = bh >> 3, h = bh & 7;
    int chunk = blockIdx.y;
    int t = threadIdx.x;

    __shared__ float s_k[16][48];
    __shared__ float s_v[16][48];
    __shared__ float s_kk[16][96];

    float acc[6][3];
#pragma unroll
    for (int i = 0; i < 6; i++)
#pragma unroll
        for (int j = 0; j < 3; j++) acc[i][j] = 0.0f;
    float kmacc[6] = {0, 0, 0, 0, 0, 0};

    int tokb = t & 15;
    float pw[6];
#pragma unroll
    for (int j = 0; j < 6; j++) {
        int u = (t >> 4) + 16 * j;
        int d = (u < 48) ? u : (u - 48);
        pw[j] = g_power[h * 48 + d];
    }

    size_t base = ((size_t)(b * NN) + (size_t)chunk * 512) * CC + h * 48;

    for (int batch = 0; batch < 32; batch++) {
        for (int e = t; e < 16 * 48; e += 256) {
            int tok = e / 48, d = e % 48;
            size_t gi = base + (size_t)(batch * 16 + tok) * CC + d;
            s_k[tok][d] = g_k[gi];
            s_v[tok][d] = g_v[gi];
        }
        __syncthreads();

#pragma unroll
        for (int j = 0; j < 6; j++) {
            int u = (t >> 4) + 16 * j;
            int d = (u < 48) ? u : (u - 48);
            float kv = s_k[tokb][d];
            float r = (u < 48) ? kv : -kv;
            float val = (r > 0.0f) ? __powf(r, pw[j]) : 0.0f;
            s_kk[tokb][u] = val;
            kmacc[j] += val;
        }
        __syncthreads();

        int u0 = (t >> 4) * 6, e0 = (t & 15) * 3;
#pragma unroll 4
        for (int tok = 0; tok < 16; tok++) {
            float v0 = s_v[tok][e0], v1 = s_v[tok][e0 + 1], v2 = s_v[tok][e0 + 2];
#pragma unroll
            for (int i = 0; i < 6; i++) {
                float ku = s_kk[tok][u0 + i];
                acc[i][0] = fmaf(ku, v0, acc[i][0]);
                acc[i][1] = fmaf(ku, v1, acc[i][1]);
                acc[i][2] = fmaf(ku, v2, acc[i][2]);
            }
        }
        __syncthreads();
    }

    int u0 = (t >> 4) * 6, e0 = (t & 15) * 3;
#pragma unroll
    for (int i = 0; i < 6; i++)
#pragma unroll
        for (int j = 0; j < 3; j++)
            atomicAdd(&g_KV[((size_t)bh * FF + u0 + i) * HD + e0 + j], acc[i][j]);
#pragma unroll
    for (int j = 0; j < 6; j++)
        atomicAdd(&g_km[(size_t)bh * FF + (t >> 4) + 16 * j], kmacc[j]);
}

// ---------------- per-token attention: qs features + z + 96x48 matvec ----------------
// grid (NN/64, BH), 256 threads; 64 tokens per block
__global__ void __launch_bounds__(256) attn_kernel() {
    int bh = blockIdx.y;
    int b = bh >> 3, h = bh & 7;
    int n0 = blockIdx.x * 64;
    int t = threadIdx.x;

    __shared__ float s_qs[64][97];
    __shared__ float s_M[96][48];
    __shared__ float s_km[96];
    __shared__ float s_z[64][2];

    float (*s_qraw)[48] = (float(*)[48])&s_M[0][0];   // 64*48 floats fit in 96*48

    size_t base = ((size_t)(b * NN) + n0) * CC + h * 48;

    // phase 1: load raw q tile + km
    for (int e = t; e < 64 * 48; e += 256) {
        int tok = e / 48, d = e % 48;
        s_qraw[tok][d] = g_q[base + (size_t)tok * CC + d];
    }
    if (t < 96) s_km[t] = g_km[(size_t)bh * FF + t] * INV_N;
    __syncthreads();

    // phase 2: qs features
    for (int idx = t; idx < 64 * 96; idx += 256) {
        int tok = idx / 96, u = idx % 96;
        int d = (u < 48) ? u : (u - 48);
        float qv = s_qraw[tok][d];
        float r = (u < 48) ? qv : -qv;
        float p = g_power[h * 48 + d];
        s_qs[tok][u] = (r > 0.0f) ? __powf(r, p) : 0.0f;
    }
    __syncthreads();

    // phase 3: z per token (reads s_qs/s_km) + load M (overwrites s_qraw region)
    if (t < 64) {
        float zs = 0.0f, zo = 0.0f;
#pragma unroll
        for (int u = 0; u < 96; u++) {
            float qv = s_qs[t][u];
            zs = fmaf(qv, s_km[u], zs);
            zo = fmaf(qv, s_km[(u + 48) % 96], zo);
        }
        s_z[t][0] = 1.0f / (zs + 1e-6f);
        s_z[t][1] = 1.0f / (zo + 1e-6f);
    }
    for (int idx = t; idx < 96 * 48; idx += 256) {
        int u = idx / 48, e = idx % 48;
        float val = (e < 24) ? g_KV[((size_t)bh * FF + u) * HD + e]
                             : g_KV[((size_t)bh * FF + ((u + 48) % 96)) * HD + e];
        s_M[u][e] = val * INV_N;
    }
    __syncthreads();

    // phase 4: 64x48 = qs(64x96) @ M(96x48), 4 tokens x 3 cols per thread
    int tg = t >> 4, eg = t & 15;
    int tok0 = tg * 4, e0 = eg * 3;
    float acc[4][3];
#pragma unroll
    for (int i = 0; i < 4; i++)
#pragma unroll
        for (int j = 0; j < 3; j++) acc[i][j] = 0.0f;

#pragma unroll 8
    for (int k = 0; k < 96; k++) {
        float a0 = s_qs[tok0][k], a1 = s_qs[tok0 + 1][k];
        float a2 = s_qs[tok0 + 2][k], a3 = s_qs[tok0 + 3][k];
        float b0 = s_M[k][e0], b1 = s_M[k][e0 + 1], b2 = s_M[k][e0 + 2];
        acc[0][0] = fmaf(a0, b0, acc[0][0]); acc[0][1] = fmaf(a0, b1, acc[0][1]); acc[0][2] = fmaf(a0, b2, acc[0][2]);
        acc[1][0] = fmaf(a1, b0, acc[1][0]); acc[1][1] = fmaf(a1, b1, acc[1][1]); acc[1][2] = fmaf(a1, b2, acc[1][2]);
        acc[2][0] = fmaf(a2, b0, acc[2][0]); acc[2][1] = fmaf(a2, b1, acc[2][1]); acc[2][2] = fmaf(a2, b2, acc[2][2]);
        acc[3][0] = fmaf(a3, b0, acc[3][0]); acc[3][1] = fmaf(a3, b1, acc[3][1]); acc[3][2] = fmaf(a3, b2, acc[3][2]);
    }

#pragma unroll
    for (int i = 0; i < 4; i++) {
        int tok = tok0 + i;
#pragma unroll
        for (int j = 0; j < 3; j++) {
            int e = e0 + j;
            float z = s_z[tok][(e < 24) ? 0 : 1];
            g_attn[base + (size_t)tok * CC + e] = acc[i][j] * z;
        }
    }
}

// ---------------- depthwise 5x5 conv + combine: pre = (attn + conv(v) + bias)*g ----------------
__global__ void __launch_bounds__(256) conv_combine_kernel(const float* __restrict__ w,
                                                           const float* __restrict__ wb) {
    __shared__ float s_w[48 * 25];
    __shared__ float s_b[48];
    int t = threadIdx.x;
    for (int i = t; i < 48 * 25; i += 256) s_w[i] = w[i];
    if (t < 48) s_b[t] = wb[t];
    __syncthreads();

    int idx = blockIdx.x * 256 + t;            // < 25,165,824
    int c = idx % CC;
    int rown = idx / CC;                        // b*N + n
    int n = rown & (NN - 1);
    int b = rown >> 14;
    int d = c % 48;
    int y = n >> 7, x = n & 127;

    float accv = s_b[d];
#pragma unroll
    for (int dy = -2; dy <= 2; dy++) {
        int yy = y + dy;
        if ((unsigned)yy < 128u) {
#pragma unroll
            for (int dx = -2; dx <= 2; dx++) {
                int xx = x + dx;
                if ((unsigned)xx < 128u) {
                    accv = fmaf(g_v[((size_t)(b << 14) + (yy << 7) + xx) * CC + c],
                                s_w[d * 25 + (dy + 2) * 5 + (dx + 2)], accv);
                }
            }
        }
    }
    float pre = (g_attn[idx] + accv) * g_g[idx];
    g_q[idx] = pre;   // reuse g_q as "pre" buffer
}

// ---------------- launch ----------------
extern "C" void kernel_launch(void* const* d_in, const int* in_sizes, int n_in,
                              void* d_out, int out_size) {
    const float* x       = (const float*)d_in[0];
    const float* W_qg    = (const float*)d_in[1];
    const float* W_kv    = (const float*)d_in[2];
    const float* W_proj  = (const float*)d_in[3];
    const float* b_proj  = (const float*)d_in[4];
    const float* pos_enc = (const float*)d_in[5];
    const float* power_p = (const float*)d_in[6];
    const float* scale_p = (const float*)d_in[7];
    const float* dwc_w   = (const float*)d_in[8];
    const float* dwc_b   = (const float*)d_in[9];
    float* out = (float*)d_out;

    prep_kernel<<<1, 384>>>(scale_p, power_p);
    zero_kv_kernel<<<(BH * FF * HD + 255) / 256, 256>>>();

    dim3 g_qg(768 / 128, ROWS / 128);
    tgemm_kernel<0><<<g_qg, 256>>>(x, W_qg, nullptr, nullptr, 768);

    dim3 g_kv(768 / 128, ROWS / 128);
    tgemm_kernel<1><<<g_kv, 256>>>(x, W_kv, pos_enc, nullptr, 768);

    dim3 g_red(BH, 32);
    reduce_kv_kernel<<<g_red, 256>>>();

    dim3 g_attn_grid(NN / 64, BH);
    attn_kernel<<<g_attn_grid, 256>>>();

    conv_combine_kernel<<<(ROWS * CC) / 256, 256>>>(dwc_w, dwc_b);

    dim3 g_proj(384 / 128, ROWS / 128);
    tgemm_kernel<2><<<g_proj, 256>>>(nullptr, W_proj, b_proj, out, 384);
}

// round 8
// speedup vs baseline: 2.2294x; 1.7662x over previous
#include <cuda_runtime.h>
#include <math.h>
#include <stdint.h>

#define BB    4
#define NN    16384
#define CC    384
#define HEADS 8
#define HD    48
#define ROWS  (BB*NN)      // 65536
#define BH    (BB*HEADS)   // 32
#define FF    96
#define INV_N (1.0f/16384.0f)

// ---------------- scratch ----------------
__device__ float g_q[ROWS*CC];      // q/scale ; later reused as "pre" (tf32-rounded)
__device__ float g_g[ROWS*CC];
__device__ float g_k[ROWS*CC];
__device__ float g_v[ROWS*CC];
__device__ float g_attn[ROWS*CC];
__device__ float g_xtf[ROWS*CC];    // x rounded to tf32
__device__ float g_KV[BH*FF*HD];
__device__ float g_km[BH*FF];
__device__ float g_scale[CC];
__device__ float g_power[CC];
__device__ float g_Wt_qg[768*384];  // B^T, tf32-rounded, [col][k]
__device__ float g_Wt_kv[768*384];
__device__ float g_Wt_pj[384*384];

// ---------------- helpers ----------------
__device__ __forceinline__ unsigned f2tf(float f) {
    unsigned r;
    asm("cvt.rna.tf32.f32 %0, %1;" : "=r"(r) : "f"(f));
    return r;
}
__device__ __forceinline__ uint32_t smem_u32(const void* p) {
    uint32_t a;
    asm("{ .reg .u64 t; cvta.to.shared.u64 t, %1; cvt.u32.u64 %0, t; }" : "=r"(a) : "l"(p));
    return a;
}
__device__ __forceinline__ void cp16(uint32_t dst, const void* src) {
    asm volatile("cp.async.cg.shared.global [%0], [%1], 16;" :: "r"(dst), "l"(src) : "memory");
}
#define CP_COMMIT() asm volatile("cp.async.commit_group;" ::: "memory")
#define CP_WAIT1()  asm volatile("cp.async.wait_group 1;" ::: "memory")
#define CP_WAIT0()  asm volatile("cp.async.wait_group 0;" ::: "memory")

__device__ __forceinline__ void ldsm4(uint32_t* f, uint32_t addr) {
    asm volatile("ldmatrix.sync.aligned.m8n8.x4.shared.b16 {%0,%1,%2,%3}, [%4];"
        : "=r"(f[0]), "=r"(f[1]), "=r"(f[2]), "=r"(f[3]) : "r"(addr));
}
__device__ __forceinline__ void mma_tf32(float d[4], const uint32_t a[4], uint32_t b0, uint32_t b1) {
    asm volatile(
        "mma.sync.aligned.m16n8k8.row.col.f32.tf32.tf32.f32 "
        "{%0,%1,%2,%3}, {%4,%5,%6,%7}, {%8,%9}, {%0,%1,%2,%3};"
        : "+f"(d[0]), "+f"(d[1]), "+f"(d[2]), "+f"(d[3])
        : "r"(a[0]), "r"(a[1]), "r"(a[2]), "r"(a[3]), "r"(b0), "r"(b1));
}

// ---------------- prep ----------------
__global__ void prep_kernel(const float* __restrict__ scale_p,
                            const float* __restrict__ power_p) {
    int c = threadIdx.x;
    if (c < CC) {
        g_scale[c] = log1pf(expf(scale_p[c]));
        g_power[c] = 1.0f + 4.0f / (1.0f + expf(-power_p[c]));
    }
}
__global__ void zero_kv_kernel() {
    int i = blockIdx.x * blockDim.x + threadIdx.x;
    if (i < BH*FF*HD) g_KV[i] = 0.0f;
    if (i < BH*FF)    g_km[i] = 0.0f;
}
__global__ void round_x_kernel(const float* __restrict__ x) {
    size_t i = ((size_t)blockIdx.x * 256 + threadIdx.x) * 4;
    float4 v = *(const float4*)(x + i);
    uint4 t;
    t.x = f2tf(v.x); t.y = f2tf(v.y); t.z = f2tf(v.z); t.w = f2tf(v.w);
    *(uint4*)(g_xtf + i) = t;
}

// ---------------- weight transpose + tf32 round: W[K][N] -> Wt[N][K] ----------------
template<int WSEL>
__global__ void transpose_cvt_kernel(const float* __restrict__ W, int K, int N) {
    float* Wt = (WSEL == 0) ? g_Wt_qg : (WSEL == 1) ? g_Wt_kv : g_Wt_pj;
    __shared__ float tile[32][33];
    int bx = blockIdx.x * 32;   // N
    int by = blockIdx.y * 32;   // K
    int tx = threadIdx.x;
#pragma unroll
    for (int ty = threadIdx.y; ty < 32; ty += 8)
        tile[ty][tx] = W[(size_t)(by + ty) * N + bx + tx];
    __syncthreads();
#pragma unroll
    for (int ty = threadIdx.y; ty < 32; ty += 8) {
        float v = tile[tx][ty];
        Wt[(size_t)(bx + ty) * K + by + tx] = __uint_as_float(f2tf(v));
    }
}

// ---------------- HMMA tf32 GEMM: CTA 128x64, BK=32, 2-stage cp.async, 48KB static smem ----------------
// 128 threads = 4 warps (2x2), warp tile 64x32, fragments via ldmatrix.x4.
// Stage s (24KB): A 16KB @ s*24576, B 8KB @ s*24576+16384 (rows 128B, SW128 swizzle).
// MODE 0: qg (A=g_xtf, Bt=g_Wt_qg), MODE 1: kv (+pos,/scale), MODE 2: proj (+bias)
#define NKT (CC/32)   // 12

template<int MODE>
__global__ void __launch_bounds__(128)
tgemm_tc(const float* __restrict__ aux, float* __restrict__ out) {
    __shared__ __align__(128) char smem[2 * 24576];   // 48KB static
    const uint32_t sbase = smem_u32(smem);
    const int tid  = threadIdx.x;
    const int lane = tid & 31;
    const int warp = tid >> 5;
    const int wm   = warp >> 1;        // 0..1
    const int wn   = warp & 1;         // 0..1
    const int row0 = blockIdx.y * 128;
    const int col0 = blockIdx.x * 64;

    const float* Ap = (MODE == 2) ? (const float*)g_q : (const float*)g_xtf;
    const float* Bt = (MODE == 0) ? (const float*)g_Wt_qg
                    : (MODE == 1) ? (const float*)g_Wt_kv
                                  : (const float*)g_Wt_pj;

    float acc[4][4][4];
#pragma unroll
    for (int i = 0; i < 4; i++)
#pragma unroll
        for (int j = 0; j < 4; j++)
#pragma unroll
            for (int f = 0; f < 4; f++) acc[i][j][f] = 0.0f;

    // per-lane ldmatrix params (fragment-role mapping verified in R3-equivalent layout)
    const int lm = lane >> 3;          // matrix index 0..3
    const int lr = lane & 7;           // row within matrix
    const int rowA = wm * 64 + (lm & 1) * 8 + lr;      // + mi*16
    const unsigned kgA = (lm >> 1) * 16;               // k-group byte offset
    const unsigned XA  = (rowA & 7) << 4;
    const int rowB = wn * 32 + (lm >> 1) * 8 + lr;     // + np*16
    const unsigned kgB = (lm & 1) * 16;
    const unsigned XB  = (rowB & 7) << 4;

    auto load_tile = [&](int kt, int s) {
        const int kb = kt * 32;
        const uint32_t dA = sbase + s * 24576;
        const uint32_t dB = dA + 16384;
#pragma unroll
        for (int i = 0; i < 8; i++) {
            int c = tid + i * 128;
            int r = c >> 3, kq = c & 7;
            unsigned off = r * 128 + kq * 16;
            off ^= (off >> 3) & 0x70;
            cp16(dA + off, Ap + (size_t)(row0 + r) * CC + kb + kq * 4);
        }
#pragma unroll
        for (int i = 0; i < 4; i++) {
            int c = tid + i * 128;
            int r = c >> 3, kq = c & 7;
            unsigned off = r * 128 + kq * 16;
            off ^= (off >> 3) & 0x70;
            cp16(dB + off, Bt + (size_t)(col0 + r) * CC + kb + kq * 4);
        }
        CP_COMMIT();
    };

    auto compute_stage = [&](int s) {
        const uint32_t bA = sbase + s * 24576;
        const uint32_t bB = bA + 16384;
#pragma unroll
        for (int ks = 0; ks < 4; ks++) {
            uint32_t af[4][4], bf[2][4];
            const unsigned colA = (unsigned)(ks * 32 + kgA) ^ XA;
            const unsigned colB = (unsigned)(ks * 32 + kgB) ^ XB;
#pragma unroll
            for (int mi = 0; mi < 4; mi++)
                ldsm4(af[mi], bA + (rowA + mi * 16) * 128 + colA);
#pragma unroll
            for (int np = 0; np < 2; np++)
                ldsm4(bf[np], bB + (rowB + np * 16) * 128 + colB);
#pragma unroll
            for (int mi = 0; mi < 4; mi++)
#pragma unroll
                for (int np = 0; np < 2; np++) {
                    mma_tf32(acc[mi][2 * np],     af[mi], bf[np][0], bf[np][1]);
                    mma_tf32(acc[mi][2 * np + 1], af[mi], bf[np][2], bf[np][3]);
                }
        }
    };

    load_tile(0, 0);
    load_tile(1, 1);

    for (int c = 0; c < NKT - 1; c++) {
        CP_WAIT1();
        __syncthreads();
        compute_stage(c & 1);
        __syncthreads();                 // all warps done reading buf (c&1) before refill
        if (c + 2 < NKT) load_tile(c + 2, c & 1);
    }
    CP_WAIT0();
    __syncthreads();
    compute_stage((NKT - 1) & 1);

    // ---- epilogue ----
    const int gq = lane >> 2;
    const int c2 = (lane & 3) * 2;
    const bool qhalf = (col0 < CC);
#pragma unroll
    for (int mi = 0; mi < 4; mi++) {
        const int rb = row0 + wm * 64 + mi * 16 + gq;
#pragma unroll
        for (int ni = 0; ni < 4; ni++) {
            const int col = col0 + wn * 32 + ni * 8 + c2;
#pragma unroll
            for (int h = 0; h < 2; h++) {
                const int r = rb + h * 8;
                float v0 = acc[mi][ni][h * 2];
                float v1 = acc[mi][ni][h * 2 + 1];
                if (MODE == 0) {
                    if (qhalf) {
                        float2 s = *(const float2*)&g_scale[col];
                        *(float2*)&g_q[(size_t)r * CC + col] = make_float2(v0 / s.x, v1 / s.y);
                    } else {
                        *(float2*)&g_g[(size_t)r * CC + (col - CC)] = make_float2(v0, v1);
                    }
                } else if (MODE == 1) {
                    if (qhalf) {
                        int n = r & (NN - 1);
                        float2 pe = *(const float2*)&aux[(size_t)n * CC + col];
                        float2 s  = *(const float2*)&g_scale[col];
                        *(float2*)&g_k[(size_t)r * CC + col] =
                            make_float2((v0 + pe.x) / s.x, (v1 + pe.y) / s.y);
                    } else {
                        *(float2*)&g_v[(size_t)r * CC + (col - CC)] = make_float2(v0, v1);
                    }
                } else {
                    float2 bb = *(const float2*)&aux[col];
                    *(float2*)&out[(size_t)r * CC + col] = make_float2(v0 + bb.x, v1 + bb.y);
                }
            }
        }
    }
}

// ---------------- reduction: KV[bh][u][e] and km[bh][u] ----------------
__global__ void __launch_bounds__(256) reduce_kv_kernel() {
    int bh = blockIdx.x;
    int b = bh >> 3, h = bh & 7;
    int chunk = blockIdx.y;
    int t = threadIdx.x;

    __shared__ float s_k[16][48];
    __shared__ float s_v[16][48];
    __shared__ float s_kk[16][96];

    float acc[6][3];
#pragma unroll
    for (int i = 0; i < 6; i++)
#pragma unroll
        for (int j = 0; j < 3; j++) acc[i][j] = 0.0f;
    float kmacc[6] = {0, 0, 0, 0, 0, 0};

    int tokb = t & 15;
    float pw[6];
#pragma unroll
    for (int j = 0; j < 6; j++) {
        int u = (t >> 4) + 16 * j;
        int d = (u < 48) ? u : (u - 48);
        pw[j] = g_power[h * 48 + d];
    }

    size_t base = ((size_t)(b * NN) + (size_t)chunk * 512) * CC + h * 48;

    for (int batch = 0; batch < 32; batch++) {
        for (int e = t; e < 16 * 48; e += 256) {
            int tok = e / 48, d = e % 48;
            size_t gi = base + (size_t)(batch * 16 + tok) * CC + d;
            s_k[tok][d] = g_k[gi];
            s_v[tok][d] = g_v[gi];
        }
        __syncthreads();

#pragma unroll
        for (int j = 0; j < 6; j++) {
            int u = (t >> 4) + 16 * j;
            int d = (u < 48) ? u : (u - 48);
            float kv = s_k[tokb][d];
            float r = (u < 48) ? kv : -kv;
            float val = (r > 0.0f) ? __powf(r, pw[j]) : 0.0f;
            s_kk[tokb][u] = val;
            kmacc[j] += val;
        }
        __syncthreads();

        int u0 = (t >> 4) * 6, e0 = (t & 15) * 3;
#pragma unroll 4
        for (int tok = 0; tok < 16; tok++) {
            float v0 = s_v[tok][e0], v1 = s_v[tok][e0 + 1], v2 = s_v[tok][e0 + 2];
#pragma unroll
            for (int i = 0; i < 6; i++) {
                float ku = s_kk[tok][u0 + i];
                acc[i][0] = fmaf(ku, v0, acc[i][0]);
                acc[i][1] = fmaf(ku, v1, acc[i][1]);
                acc[i][2] = fmaf(ku, v2, acc[i][2]);
            }
        }
        __syncthreads();
    }

    int u0 = (t >> 4) * 6, e0 = (t & 15) * 3;
#pragma unroll
    for (int i = 0; i < 6; i++)
#pragma unroll
        for (int j = 0; j < 3; j++)
            atomicAdd(&g_KV[((size_t)bh * FF + u0 + i) * HD + e0 + j], acc[i][j]);
#pragma unroll
    for (int j = 0; j < 6; j++)
        atomicAdd(&g_km[(size_t)bh * FF + (t >> 4) + 16 * j], kmacc[j]);
}

// ---------------- per-token attention ----------------
__global__ void __launch_bounds__(256) attn_kernel() {
    int bh = blockIdx.y;
    int b = bh >> 3, h = bh & 7;
    int n0 = blockIdx.x * 64;
    int t = threadIdx.x;

    __shared__ float s_qs[64][97];
    __shared__ float s_M[96][48];
    __shared__ float s_km[96];
    __shared__ float s_z[64][2];

    float (*s_qraw)[48] = (float(*)[48])&s_M[0][0];

    size_t base = ((size_t)(b * NN) + n0) * CC + h * 48;

    for (int e = t; e < 64 * 48; e += 256) {
        int tok = e / 48, d = e % 48;
        s_qraw[tok][d] = g_q[base + (size_t)tok * CC + d];
    }
    if (t < 96) s_km[t] = g_km[(size_t)bh * FF + t] * INV_N;
    __syncthreads();

    for (int idx = t; idx < 64 * 96; idx += 256) {
        int tok = idx / 96, u = idx % 96;
        int d = (u < 48) ? u : (u - 48);
        float qv = s_qraw[tok][d];
        float r = (u < 48) ? qv : -qv;
        float p = g_power[h * 48 + d];
        s_qs[tok][u] = (r > 0.0f) ? __powf(r, p) : 0.0f;
    }
    __syncthreads();

    if (t < 64) {
        float zs = 0.0f, zo = 0.0f;
#pragma unroll
        for (int u = 0; u < 96; u++) {
            float qv = s_qs[t][u];
            zs = fmaf(qv, s_km[u], zs);
            zo = fmaf(qv, s_km[(u + 48) % 96], zo);
        }
        s_z[t][0] = 1.0f / (zs + 1e-6f);
        s_z[t][1] = 1.0f / (zo + 1e-6f);
    }
    for (int idx = t; idx < 96 * 48; idx += 256) {
        int u = idx / 48, e = idx % 48;
        float val = (e < 24) ? g_KV[((size_t)bh * FF + u) * HD + e]
                             : g_KV[((size_t)bh * FF + ((u + 48) % 96)) * HD + e];
        s_M[u][e] = val * INV_N;
    }
    __syncthreads();

    int tg = t >> 4, eg = t & 15;
    int tok0 = tg * 4, e0 = eg * 3;
    float acc[4][3];
#pragma unroll
    for (int i = 0; i < 4; i++)
#pragma unroll
        for (int j = 0; j < 3; j++) acc[i][j] = 0.0f;

#pragma unroll 8
    for (int k = 0; k < 96; k++) {
        float a0 = s_qs[tok0][k], a1 = s_qs[tok0 + 1][k];
        float a2 = s_qs[tok0 + 2][k], a3 = s_qs[tok0 + 3][k];
        float b0 = s_M[k][e0], b1 = s_M[k][e0 + 1], b2 = s_M[k][e0 + 2];
        acc[0][0] = fmaf(a0, b0, acc[0][0]); acc[0][1] = fmaf(a0, b1, acc[0][1]); acc[0][2] = fmaf(a0, b2, acc[0][2]);
        acc[1][0] = fmaf(a1, b0, acc[1][0]); acc[1][1] = fmaf(a1, b1, acc[1][1]); acc[1][2] = fmaf(a1, b2, acc[1][2]);
        acc[2][0] = fmaf(a2, b0, acc[2][0]); acc[2][1] = fmaf(a2, b1, acc[2][1]); acc[2][2] = fmaf(a2, b2, acc[2][2]);
        acc[3][0] = fmaf(a3, b0, acc[3][0]); acc[3][1] = fmaf(a3, b1, acc[3][1]); acc[3][2] = fmaf(a3, b2, acc[3][2]);
    }

#pragma unroll
    for (int i = 0; i < 4; i++) {
        int tok = tok0 + i;
#pragma unroll
        for (int j = 0; j < 3; j++) {
            int e = e0 + j;
            float z = s_z[tok][(e < 24) ? 0 : 1];
            g_attn[base + (size_t)tok * CC + e] = acc[i][j] * z;
        }
    }
}

// ---------------- depthwise conv + combine (writes tf32-rounded pre) ----------------
__global__ void __launch_bounds__(256) conv_combine_kernel(const float* __restrict__ w,
                                                           const float* __restrict__ wb) {
    __shared__ float s_w[48 * 25];
    __shared__ float s_b[48];
    int t = threadIdx.x;
    for (int i = t; i < 48 * 25; i += 256) s_w[i] = w[i];
    if (t < 48) s_b[t] = wb[t];
    __syncthreads();

    int idx = blockIdx.x * 256 + t;
    int c = idx % CC;
    int rown = idx / CC;
    int n = rown & (NN - 1);
    int b = rown >> 14;
    int d = c % 48;
    int y = n >> 7, x = n & 127;

    float accv = s_b[d];
#pragma unroll
    for (int dy = -2; dy <= 2; dy++) {
        int yy = y + dy;
        if ((unsigned)yy < 128u) {
#pragma unroll
            for (int dx = -2; dx <= 2; dx++) {
                int xx = x + dx;
                if ((unsigned)xx < 128u) {
                    accv = fmaf(g_v[((size_t)(b << 14) + (yy << 7) + xx) * CC + c],
                                s_w[d * 25 + (dy + 2) * 5 + (dx + 2)], accv);
                }
            }
        }
    }
    float pre = (g_attn[idx] + accv) * g_g[idx];
    g_q[idx] = __uint_as_float(f2tf(pre));   // tf32-rounded for the proj GEMM
}

// ---------------- launch (kernel launches ONLY — no host API calls) ----------------
extern "C" void kernel_launch(void* const* d_in, const int* in_sizes, int n_in,
                              void* d_out, int out_size) {
    const float* x       = (const float*)d_in[0];
    const float* W_qg    = (const float*)d_in[1];
    const float* W_kv    = (const float*)d_in[2];
    const float* W_proj  = (const float*)d_in[3];
    const float* b_proj  = (const float*)d_in[4];
    const float* pos_enc = (const float*)d_in[5];
    const float* power_p = (const float*)d_in[6];
    const float* scale_p = (const float*)d_in[7];
    const float* dwc_w   = (const float*)d_in[8];
    const float* dwc_b   = (const float*)d_in[9];
    float* out = (float*)d_out;

    prep_kernel<<<1, 384>>>(scale_p, power_p);
    zero_kv_kernel<<<(BH * FF * HD + 255) / 256, 256>>>();
    round_x_kernel<<<(ROWS * CC) / 1024, 256>>>(x);

    transpose_cvt_kernel<0><<<dim3(768 / 32, 384 / 32), dim3(32, 8)>>>(W_qg, 384, 768);
    transpose_cvt_kernel<1><<<dim3(768 / 32, 384 / 32), dim3(32, 8)>>>(W_kv, 384, 768);
    transpose_cvt_kernel<2><<<dim3(384 / 32, 384 / 32), dim3(32, 8)>>>(W_proj, 384, 384);

    tgemm_tc<0><<<dim3(12, ROWS / 128), 128>>>(nullptr, nullptr);
    tgemm_tc<1><<<dim3(12, ROWS / 128), 128>>>(pos_enc, nullptr);

    reduce_kv_kernel<<<dim3(BH, 32), 256>>>();
    attn_kernel<<<dim3(NN / 64, BH), 256>>>();
    conv_combine_kernel<<<(ROWS * CC) / 256, 256>>>(dwc_w, dwc_b);

    tgemm_tc<2><<<dim3(6, ROWS / 128), 128>>>(b_proj, out);
}

// round 13
// speedup vs baseline: 2.5039x; 1.1232x over previous
#include <cuda_runtime.h>
#include <math.h>
#include <stdint.h>

#define BB    4
#define NN    16384
#define CC    384
#define HEADS 8
#define HD    48
#define ROWS  (BB*NN)      // 65536
#define BH    (BB*HEADS)   // 32
#define FF    96
#define INV_N (1.0f/16384.0f)

// ---------------- scratch ----------------
__device__ float g_q[ROWS*CC];      // q/scale ; later reused as "pre" (tf32-rounded)
__device__ float g_g[ROWS*CC];
__device__ float g_k[ROWS*CC];
__device__ float g_v[ROWS*CC];
__device__ float g_attn[ROWS*CC];
__device__ float g_xtf[ROWS*CC];    // x rounded to tf32
__device__ float g_KV[BH*FF*HD];
__device__ float g_km[BH*FF];
__device__ float g_scale[CC];
__device__ float g_power[CC];
__device__ float g_Wt_qg[768*384];  // B^T, tf32-rounded, [col][k]
__device__ float g_Wt_kv[768*384];
__device__ float g_Wt_pj[384*384];

// ---------------- helpers ----------------
__device__ __forceinline__ unsigned f2tf(float f) {
    unsigned r;
    asm("cvt.rna.tf32.f32 %0, %1;" : "=r"(r) : "f"(f));
    return r;
}
__device__ __forceinline__ uint32_t smem_u32(const void* p) {
    uint32_t a;
    asm("{ .reg .u64 t; cvta.to.shared.u64 t, %1; cvt.u32.u64 %0, t; }" : "=r"(a) : "l"(p));
    return a;
}
__device__ __forceinline__ void cp16(uint32_t dst, const void* src) {
    asm volatile("cp.async.cg.shared.global [%0], [%1], 16;" :: "r"(dst), "l"(src) : "memory");
}
#define CP_COMMIT() asm volatile("cp.async.commit_group;" ::: "memory")
#define CP_WAIT1()  asm volatile("cp.async.wait_group 1;" ::: "memory")
#define CP_WAIT0()  asm volatile("cp.async.wait_group 0;" ::: "memory")

__device__ __forceinline__ void ldsm4(uint32_t* f, uint32_t addr) {
    asm volatile("ldmatrix.sync.aligned.m8n8.x4.shared.b16 {%0,%1,%2,%3}, [%4];"
        : "=r"(f[0]), "=r"(f[1]), "=r"(f[2]), "=r"(f[3]) : "r"(addr));
}
__device__ __forceinline__ void mma_tf32(float d[4], const uint32_t a[4], uint32_t b0, uint32_t b1) {
    asm volatile(
        "mma.sync.aligned.m16n8k8.row.col.f32.tf32.tf32.f32 "
        "{%0,%1,%2,%3}, {%4,%5,%6,%7}, {%8,%9}, {%0,%1,%2,%3};"
        : "+f"(d[0]), "+f"(d[1]), "+f"(d[2]), "+f"(d[3])
        : "r"(a[0]), "r"(a[1]), "r"(a[2]), "r"(a[3]), "r"(b0), "r"(b1));
}

// ---------------- prep ----------------
__global__ void prep_kernel(const float* __restrict__ scale_p,
                            const float* __restrict__ power_p) {
    int c = threadIdx.x;
    if (c < CC) {
        g_scale[c] = log1pf(expf(scale_p[c]));
        g_power[c] = 1.0f + 4.0f / (1.0f + expf(-power_p[c]));
    }
}
__global__ void zero_kv_kernel() {
    int i = blockIdx.x * blockDim.x + threadIdx.x;
    if (i < BH*FF*HD) g_KV[i] = 0.0f;
    if (i < BH*FF)    g_km[i] = 0.0f;
}
__global__ void round_x_kernel(const float* __restrict__ x) {
    size_t i = ((size_t)blockIdx.x * 256 + threadIdx.x) * 4;
    float4 v = *(const float4*)(x + i);
    uint4 t;
    t.x = f2tf(v.x); t.y = f2tf(v.y); t.z = f2tf(v.z); t.w = f2tf(v.w);
    *(uint4*)(g_xtf + i) = t;
}

// ---------------- weight transpose + tf32 round: W[K][N] -> Wt[N][K] ----------------
template<int WSEL>
__global__ void transpose_cvt_kernel(const float* __restrict__ W, int K, int N) {
    float* Wt = (WSEL == 0) ? g_Wt_qg : (WSEL == 1) ? g_Wt_kv : g_Wt_pj;
    __shared__ float tile[32][33];
    int bx = blockIdx.x * 32;   // N
    int by = blockIdx.y * 32;   // K
    int tx = threadIdx.x;
#pragma unroll
    for (int ty = threadIdx.y; ty < 32; ty += 8)
        tile[ty][tx] = W[(size_t)(by + ty) * N + bx + tx];
    __syncthreads();
#pragma unroll
    for (int ty = threadIdx.y; ty < 32; ty += 8) {
        float v = tile[tx][ty];
        Wt[(size_t)(bx + ty) * K + by + tx] = __uint_as_float(f2tf(v));
    }
}

// ---------------- HMMA tf32 GEMM (unchanged from R8 — proven) ----------------
#define NKT (CC/32)   // 12

template<int MODE>
__global__ void __launch_bounds__(128)
tgemm_tc(const float* __restrict__ aux, float* __restrict__ out) {
    __shared__ __align__(128) char smem[2 * 24576];   // 48KB static
    const uint32_t sbase = smem_u32(smem);
    const int tid  = threadIdx.x;
    const int lane = tid & 31;
    const int warp = tid >> 5;
    const int wm   = warp >> 1;
    const int wn   = warp & 1;
    const int row0 = blockIdx.y * 128;
    const int col0 = blockIdx.x * 64;

    const float* Ap = (MODE == 2) ? (const float*)g_q : (const float*)g_xtf;
    const float* Bt = (MODE == 0) ? (const float*)g_Wt_qg
                    : (MODE == 1) ? (const float*)g_Wt_kv
                                  : (const float*)g_Wt_pj;

    float acc[4][4][4];
#pragma unroll
    for (int i = 0; i < 4; i++)
#pragma unroll
        for (int j = 0; j < 4; j++)
#pragma unroll
            for (int f = 0; f < 4; f++) acc[i][j][f] = 0.0f;

    const int lm = lane >> 3;
    const int lr = lane & 7;
    const int rowA = wm * 64 + (lm & 1) * 8 + lr;
    const unsigned kgA = (lm >> 1) * 16;
    const unsigned XA  = (rowA & 7) << 4;
    const int rowB = wn * 32 + (lm >> 1) * 8 + lr;
    const unsigned kgB = (lm & 1) * 16;
    const unsigned XB  = (rowB & 7) << 4;

    auto load_tile = [&](int kt, int s) {
        const int kb = kt * 32;
        const uint32_t dA = sbase + s * 24576;
        const uint32_t dB = dA + 16384;
#pragma unroll
        for (int i = 0; i < 8; i++) {
            int c = tid + i * 128;
            int r = c >> 3, kq = c & 7;
            unsigned off = r * 128 + kq * 16;
            off ^= (off >> 3) & 0x70;
            cp16(dA + off, Ap + (size_t)(row0 + r) * CC + kb + kq * 4);
        }
#pragma unroll
        for (int i = 0; i < 4; i++) {
            int c = tid + i * 128;
            int r = c >> 3, kq = c & 7;
            unsigned off = r * 128 + kq * 16;
            off ^= (off >> 3) & 0x70;
            cp16(dB + off, Bt + (size_t)(col0 + r) * CC + kb + kq * 4);
        }
        CP_COMMIT();
    };

    auto compute_stage = [&](int s) {
        const uint32_t bA = sbase + s * 24576;
        const uint32_t bB = bA + 16384;
#pragma unroll
        for (int ks = 0; ks < 4; ks++) {
            uint32_t af[4][4], bf[2][4];
            const unsigned colA = (unsigned)(ks * 32 + kgA) ^ XA;
            const unsigned colB = (unsigned)(ks * 32 + kgB) ^ XB;
#pragma unroll
            for (int mi = 0; mi < 4; mi++)
                ldsm4(af[mi], bA + (rowA + mi * 16) * 128 + colA);
#pragma unroll
            for (int np = 0; np < 2; np++)
                ldsm4(bf[np], bB + (rowB + np * 16) * 128 + colB);
#pragma unroll
            for (int mi = 0; mi < 4; mi++)
#pragma unroll
                for (int np = 0; np < 2; np++) {
                    mma_tf32(acc[mi][2 * np],     af[mi], bf[np][0], bf[np][1]);
                    mma_tf32(acc[mi][2 * np + 1], af[mi], bf[np][2], bf[np][3]);
                }
        }
    };

    load_tile(0, 0);
    load_tile(1, 1);

    for (int c = 0; c < NKT - 1; c++) {
        CP_WAIT1();
        __syncthreads();
        compute_stage(c & 1);
        __syncthreads();
        if (c + 2 < NKT) load_tile(c + 2, c & 1);
    }
    CP_WAIT0();
    __syncthreads();
    compute_stage((NKT - 1) & 1);

    const int gq = lane >> 2;
    const int c2 = (lane & 3) * 2;
    const bool qhalf = (col0 < CC);
#pragma unroll
    for (int mi = 0; mi < 4; mi++) {
        const int rb = row0 + wm * 64 + mi * 16 + gq;
#pragma unroll
        for (int ni = 0; ni < 4; ni++) {
            const int col = col0 + wn * 32 + ni * 8 + c2;
#pragma unroll
            for (int h = 0; h < 2; h++) {
                const int r = rb + h * 8;
                float v0 = acc[mi][ni][h * 2];
                float v1 = acc[mi][ni][h * 2 + 1];
                if (MODE == 0) {
                    if (qhalf) {
                        float2 s = *(const float2*)&g_scale[col];
                        *(float2*)&g_q[(size_t)r * CC + col] = make_float2(v0 / s.x, v1 / s.y);
                    } else {
                        *(float2*)&g_g[(size_t)r * CC + (col - CC)] = make_float2(v0, v1);
                    }
                } else if (MODE == 1) {
                    if (qhalf) {
                        int n = r & (NN - 1);
                        float2 pe = *(const float2*)&aux[(size_t)n * CC + col];
                        float2 s  = *(const float2*)&g_scale[col];
                        *(float2*)&g_k[(size_t)r * CC + col] =
                            make_float2((v0 + pe.x) / s.x, (v1 + pe.y) / s.y);
                    } else {
                        *(float2*)&g_v[(size_t)r * CC + (col - CC)] = make_float2(v0, v1);
                    }
                } else {
                    float2 bb = *(const float2*)&aux[col];
                    *(float2*)&out[(size_t)r * CC + col] = make_float2(v0 + bb.x, v1 + bb.y);
                }
            }
        }
    }
}

// ---------------- reduction: KV[bh][u][e] and km[bh][u] (vectorized) ----------------
// grid (BH, 32 chunks of 512 tokens), 256 threads; batches of 32 tokens.
__global__ void __launch_bounds__(256) reduce_kv_kernel() {
    int bh = blockIdx.x;
    int b = bh >> 3, h = bh & 7;
    int chunk = blockIdx.y;
    int t = threadIdx.x;

    __shared__ float s_kraw[32][49];   // raw k batch (odd pad: conflict-free col reads)
    __shared__ float s_vT[48][36];     // v transposed (rows 144B, 16B-aligned)
    __shared__ float s_kkT[96][36];    // features transposed

    const int tok_l = t & 31;          // feature-phase token
    const int ubase = t >> 5;          // warp id: all lanes share the u-set
    float pw[12];
#pragma unroll
    for (int j = 0; j < 12; j++) {
        int u = ubase + 8 * j;
        int d = (u < 48) ? u : (u - 48);
        pw[j] = g_power[h * 48 + d];
    }
    float kmacc[12];
#pragma unroll
    for (int j = 0; j < 12; j++) kmacc[j] = 0.0f;

    const int ug = t >> 4, eg = t & 15;
    const int u0 = ug * 6, e0 = eg * 3;
    float acc[6][3];
#pragma unroll
    for (int i = 0; i < 6; i++)
#pragma unroll
        for (int j = 0; j < 3; j++) acc[i][j] = 0.0f;

    size_t base = ((size_t)(b * NN) + (size_t)chunk * 512) * CC + h * 48;

    for (int batch = 0; batch < 16; batch++) {
        // load 32 tokens of k (row-major) and v (transposed), coalesced gmem reads
#pragma unroll
        for (int i = 0; i < 6; i++) {
            int e = t + i * 256;       // < 1536
            int tok = e / 48, dd = e % 48;
            size_t gi = base + (size_t)(batch * 32 + tok) * CC + dd;
            s_kraw[tok][dd] = g_k[gi];
            s_vT[dd][tok]   = g_v[gi];
        }
        __syncthreads();

        // features: thread handles token tok_l, 12 u's (u = ubase + 8j)
#pragma unroll
        for (int j = 0; j < 12; j++) {
            int u = ubase + 8 * j;
            int d = (u < 48) ? u : (u - 48);
            float kv = s_kraw[tok_l][d];
            float r = (u < 48) ? kv : -kv;
            float val = (r > 0.0f) ? __powf(r, pw[j]) : 0.0f;
            s_kkT[u][tok_l] = val;
            kmacc[j] += val;
        }
        __syncthreads();

        // accumulate: float4 over tokens, 72 FMA per 9 LDS.128
#pragma unroll
        for (int tc = 0; tc < 32; tc += 4) {
            float4 kk[6], vv[3];
#pragma unroll
            for (int i = 0; i < 6; i++) kk[i] = *(const float4*)&s_kkT[u0 + i][tc];
#pragma unroll
            for (int j = 0; j < 3; j++) vv[j] = *(const float4*)&s_vT[e0 + j][tc];
#pragma unroll
            for (int i = 0; i < 6; i++) {
                const float* kf = (const float*)&kk[i];
#pragma unroll
                for (int j = 0; j < 3; j++) {
                    const float* vf = (const float*)&vv[j];
                    acc[i][j] = fmaf(kf[0], vf[0], acc[i][j]);
                    acc[i][j] = fmaf(kf[1], vf[1], acc[i][j]);
                    acc[i][j] = fmaf(kf[2], vf[2], acc[i][j]);
                    acc[i][j] = fmaf(kf[3], vf[3], acc[i][j]);
                }
            }
        }
        __syncthreads();
    }

#pragma unroll
    for (int i = 0; i < 6; i++)
#pragma unroll
        for (int j = 0; j < 3; j++)
            atomicAdd(&g_KV[((size_t)bh * FF + u0 + i) * HD + e0 + j], acc[i][j]);

    // km: warp-reduce (all lanes share u-set), lane 0 commits
#pragma unroll
    for (int j = 0; j < 12; j++) {
        float v = kmacc[j];
#pragma unroll
        for (int off = 16; off > 0; off >>= 1)
            v += __shfl_xor_sync(0xFFFFFFFFu, v, off);
        if ((t & 31) == 0)
            atomicAdd(&g_km[(size_t)bh * FF + ubase + 8 * j], v);
    }
}

// ---------------- per-token attention (vectorized matvec) ----------------
// grid (NN/64, BH), 256 threads; 64 tokens per block
__global__ void __launch_bounds__(256) attn_kernel() {
    int bh = blockIdx.y;
    int b = bh >> 3, h = bh & 7;
    int n0 = blockIdx.x * 64;
    int t = threadIdx.x;

    __shared__ float s_qsT[96][68];    // features transposed (272B rows, 16B-aligned)
    __shared__ float s_MT[48][100];    // M transposed [e][u] (400B rows, 16B-aligned)
    __shared__ float s_km[96];
    __shared__ float s_z[64][2];

    float (*s_qraw)[49] = (float(*)[49])&s_MT[0][0];   // 64*49 = 3136 <= 4800 floats

    size_t base = ((size_t)(b * NN) + n0) * CC + h * 48;

    // phase 1: raw q tile (odd-padded rows) + km
    for (int e = t; e < 64 * 48; e += 256) {
        int tok = e / 48, d = e % 48;
        s_qraw[tok][d] = g_q[base + (size_t)tok * CC + d];
    }
    if (t < 96) s_km[t] = g_km[(size_t)bh * FF + t] * INV_N;
    __syncthreads();

    // phase 2: features -> s_qsT[u][tok] (consecutive lanes = consecutive tok)
    for (int idx = t; idx < 96 * 64; idx += 256) {
        int u = idx >> 6, tok = idx & 63;
        int d = (u < 48) ? u : (u - 48);
        float qv = s_qraw[tok][d];
        float r = (u < 48) ? qv : -qv;
        float p = g_power[h * 48 + d];
        s_qsT[u][tok] = (r > 0.0f) ? __powf(r, p) : 0.0f;
    }
    __syncthreads();

    // phase 3: z per token + M load (overwrites s_qraw alias)
    if (t < 64) {
        float zs = 0.0f, zo = 0.0f;
#pragma unroll
        for (int u = 0; u < 96; u++) {
            float qv = s_qsT[u][t];
            zs = fmaf(qv, s_km[u], zs);
            zo = fmaf(qv, s_km[(u + 48) % 96], zo);
        }
        s_z[t][0] = 1.0f / (zs + 1e-6f);
        s_z[t][1] = 1.0f / (zo + 1e-6f);
    }
    for (int idx = t; idx < 48 * 96; idx += 256) {
        int e = idx / 96, u = idx % 96;
        int usrc = (e < 24) ? u : ((u + 48) % 96);
        s_MT[e][u] = g_KV[((size_t)bh * FF + usrc) * HD + e] * INV_N;
    }
    __syncthreads();

    // phase 4: out[64][48] = qsT^T @ MT^T via float4 chunks over u
    const int tg = t >> 4, eg = t & 15;
    const int tok0 = tg * 4, e0 = eg * 3;
    float acc[4][3];
#pragma unroll
    for (int i = 0; i < 4; i++)
#pragma unroll
        for (int j = 0; j < 3; j++) acc[i][j] = 0.0f;

#pragma unroll 4
    for (int k = 0; k < 96; k += 4) {
        float4 qa[4], mb[3];
#pragma unroll
        for (int kk2 = 0; kk2 < 4; kk2++) qa[kk2] = *(const float4*)&s_qsT[k + kk2][tok0];
#pragma unroll
        for (int j = 0; j < 3; j++) mb[j] = *(const float4*)&s_MT[e0 + j][k];
#pragma unroll
        for (int kk2 = 0; kk2 < 4; kk2++) {
            const float* qf = (const float*)&qa[kk2];
#pragma unroll
            for (int j = 0; j < 3; j++) {
                const float* mf = (const float*)&mb[j];
                float mv = mf[kk2];
                acc[0][j] = fmaf(qf[0], mv, acc[0][j]);
                acc[1][j] = fmaf(qf[1], mv, acc[1][j]);
                acc[2][j] = fmaf(qf[2], mv, acc[2][j]);
                acc[3][j] = fmaf(qf[3], mv, acc[3][j]);
            }
        }
    }

#pragma unroll
    for (int i = 0; i < 4; i++) {
        int tok = tok0 + i;
#pragma unroll
        for (int j = 0; j < 3; j++) {
            int e = e0 + j;
            float z = s_z[tok][(e < 24) ? 0 : 1];
            g_attn[base + (size_t)tok * CC + e] = acc[i][j] * z;
        }
    }
}

// ---------------- depthwise conv + combine, float4 channels ----------------
__global__ void __launch_bounds__(256) conv_combine_kernel(const float* __restrict__ w,
                                                           const float* __restrict__ wb) {
    __shared__ float s_w4[25][48];     // [tap][d]
    __shared__ float s_b[48];
    int t = threadIdx.x;
    for (int i = t; i < 25 * 48; i += 256) {
        int tap = i % 25, d = i / 25;
        s_w4[tap][d] = w[d * 25 + tap];
    }
    if (t < 48) s_b[t] = wb[t];
    __syncthreads();

    int idx = blockIdx.x * 256 + t;            // element-quad index < 6,291,456
    int c4 = idx % 96;                          // CC/4
    int rown = idx / 96;                        // b*N + n
    int c = c4 * 4;
    int n = rown & (NN - 1);
    int b = rown >> 14;
    int d = c % 48;                             // 4 | 48 -> d..d+3 same head
    int y = n >> 7, x = n & 127;

    float4 bv = *(const float4*)&s_b[d];
    float a0 = bv.x, a1 = bv.y, a2 = bv.z, a3 = bv.w;
#pragma unroll
    for (int dy = -2; dy <= 2; dy++) {
        int yy = y + dy;
        if ((unsigned)yy < 128u) {
#pragma unroll
            for (int dx = -2; dx <= 2; dx++) {
                int xx = x + dx;
                if ((unsigned)xx < 128u) {
                    int tap = (dy + 2) * 5 + (dx + 2);
                    float4 vv = *(const float4*)&g_v[((size_t)(b << 14) + (yy << 7) + xx) * CC + c];
                    float4 ww = *(const float4*)&s_w4[tap][d];
                    a0 = fmaf(vv.x, ww.x, a0);
                    a1 = fmaf(vv.y, ww.y, a1);
                    a2 = fmaf(vv.z, ww.z, a2);
                    a3 = fmaf(vv.w, ww.w, a3);
                }
            }
        }
    }
    size_t gi = (size_t)idx * 4;               // == rown*CC + c
    float4 at = *(const float4*)&g_attn[gi];
    float4 gg = *(const float4*)&g_g[gi];
    uint4 o;
    o.x = f2tf((at.x + a0) * gg.x);
    o.y = f2tf((at.y + a1) * gg.y);
    o.z = f2tf((at.z + a2) * gg.z);
    o.w = f2tf((at.w + a3) * gg.w);
    *(uint4*)&g_q[gi] = o;                     // tf32-rounded "pre" for proj GEMM
}

// ---------------- launch (kernel launches ONLY) ----------------
extern "C" void kernel_launch(void* const* d_in, const int* in_sizes, int n_in,
                              void* d_out, int out_size) {
    const float* x       = (const float*)d_in[0];
    const float* W_qg    = (const float*)d_in[1];
    const float* W_kv    = (const float*)d_in[2];
    const float* W_proj  = (const float*)d_in[3];
    const float* b_proj  = (const float*)d_in[4];
    const float* pos_enc = (const float*)d_in[5];
    const float* power_p = (const float*)d_in[6];
    const float* scale_p = (const float*)d_in[7];
    const float* dwc_w   = (const float*)d_in[8];
    const float* dwc_b   = (const float*)d_in[9];
    float* out = (float*)d_out;

    prep_kernel<<<1, 384>>>(scale_p, power_p);
    zero_kv_kernel<<<(BH * FF * HD + 255) / 256, 256>>>();
    round_x_kernel<<<(ROWS * CC) / 1024, 256>>>(x);

    transpose_cvt_kernel<0><<<dim3(768 / 32, 384 / 32), dim3(32, 8)>>>(W_qg, 384, 768);
    transpose_cvt_kernel<1><<<dim3(768 / 32, 384 / 32), dim3(32, 8)>>>(W_kv, 384, 768);
    transpose_cvt_kernel<2><<<dim3(384 / 32, 384 / 32), dim3(32, 8)>>>(W_proj, 384, 384);

    tgemm_tc<0><<<dim3(12, ROWS / 128), 128>>>(nullptr, nullptr);
    tgemm_tc<1><<<dim3(12, ROWS / 128), 128>>>(pos_enc, nullptr);

    reduce_kv_kernel<<<dim3(BH, 32), 256>>>();
    attn_kernel<<<dim3(NN / 64, BH), 256>>>();
    conv_combine_kernel<<<(ROWS * CC / 4) / 256, 256>>>(dwc_w, dwc_b);

    tgemm_tc<2><<<dim3(6, ROWS / 128), 128>>>(b_proj, out);
}

// round 14
// speedup vs baseline: 2.8875x; 1.1532x over previous
#include <cuda_runtime.h>
#include <math.h>
#include <stdint.h>

#define BB    4
#define NN    16384
#define CC    384
#define HEADS 8
#define HD    48
#define ROWS  (BB*NN)      // 65536
#define BH    (BB*HEADS)   // 32
#define FF    96
#define INV_N (1.0f/16384.0f)

// ---------------- scratch ----------------
__device__ float g_q[ROWS*CC];      // q/scale ; later reused as "pre" (tf32-rounded)
__device__ float g_g[ROWS*CC];
__device__ float g_k[ROWS*CC];
__device__ float g_v[ROWS*CC];
__device__ float g_attn[ROWS*CC];
__device__ float g_xtf[ROWS*CC];    // x rounded to tf32
__device__ float g_KV[BH*FF*HD];
__device__ float g_km[BH*FF];
__device__ float g_scale[CC];
__device__ float g_power[CC];
__device__ float g_Wt_qg[768*384];  // B^T, tf32-rounded, [col][k]
__device__ float g_Wt_kv[768*384];
__device__ float g_Wt_pj[384*384];

// ---------------- helpers ----------------
__device__ __forceinline__ unsigned f2tf(float f) {
    unsigned r;
    asm("cvt.rna.tf32.f32 %0, %1;" : "=r"(r) : "f"(f));
    return r;
}
__device__ __forceinline__ uint32_t smem_u32(const void* p) {
    uint32_t a;
    asm("{ .reg .u64 t; cvta.to.shared.u64 t, %1; cvt.u32.u64 %0, t; }" : "=r"(a) : "l"(p));
    return a;
}
__device__ __forceinline__ void cp16(uint32_t dst, const void* src) {
    asm volatile("cp.async.cg.shared.global [%0], [%1], 16;" :: "r"(dst), "l"(src) : "memory");
}
#define CP_COMMIT() asm volatile("cp.async.commit_group;" ::: "memory")
#define CP_WAIT1()  asm volatile("cp.async.wait_group 1;" ::: "memory")
#define CP_WAIT0()  asm volatile("cp.async.wait_group 0;" ::: "memory")

__device__ __forceinline__ void ldsm4(uint32_t* f, uint32_t addr) {
    asm volatile("ldmatrix.sync.aligned.m8n8.x4.shared.b16 {%0,%1,%2,%3}, [%4];"
        : "=r"(f[0]), "=r"(f[1]), "=r"(f[2]), "=r"(f[3]) : "r"(addr));
}
__device__ __forceinline__ void mma_tf32(float d[4], const uint32_t a[4], uint32_t b0, uint32_t b1) {
    asm volatile(
        "mma.sync.aligned.m16n8k8.row.col.f32.tf32.tf32.f32 "
        "{%0,%1,%2,%3}, {%4,%5,%6,%7}, {%8,%9}, {%0,%1,%2,%3};"
        : "+f"(d[0]), "+f"(d[1]), "+f"(d[2]), "+f"(d[3])
        : "r"(a[0]), "r"(a[1]), "r"(a[2]), "r"(a[3]), "r"(b0), "r"(b1));
}

// ---------------- prep ----------------
__global__ void prep_kernel(const float* __restrict__ scale_p,
                            const float* __restrict__ power_p) {
    int c = threadIdx.x;
    if (c < CC) {
        g_scale[c] = log1pf(expf(scale_p[c]));
        g_power[c] = 1.0f + 4.0f / (1.0f + expf(-power_p[c]));
    }
}
__global__ void zero_kv_kernel() {
    int i = blockIdx.x * blockDim.x + threadIdx.x;
    if (i < BH*FF*HD) g_KV[i] = 0.0f;
    if (i < BH*FF)    g_km[i] = 0.0f;
}
__global__ void round_x_kernel(const float* __restrict__ x) {
    size_t i = ((size_t)blockIdx.x * 256 + threadIdx.x) * 4;
    float4 v = *(const float4*)(x + i);
    uint4 t;
    t.x = f2tf(v.x); t.y = f2tf(v.y); t.z = f2tf(v.z); t.w = f2tf(v.w);
    *(uint4*)(g_xtf + i) = t;
}

// ---------------- weight transpose + tf32 round: W[K][N] -> Wt[N][K] ----------------
template<int WSEL>
__global__ void transpose_cvt_kernel(const float* __restrict__ W, int K, int N) {
    float* Wt = (WSEL == 0) ? g_Wt_qg : (WSEL == 1) ? g_Wt_kv : g_Wt_pj;
    __shared__ float tile[32][33];
    int bx = blockIdx.x * 32;   // N
    int by = blockIdx.y * 32;   // K
    int tx = threadIdx.x;
#pragma unroll
    for (int ty = threadIdx.y; ty < 32; ty += 8)
        tile[ty][tx] = W[(size_t)(by + ty) * N + bx + tx];
    __syncthreads();
#pragma unroll
    for (int ty = threadIdx.y; ty < 32; ty += 8) {
        float v = tile[tx][ty];
        Wt[(size_t)(bx + ty) * K + by + tx] = __uint_as_float(f2tf(v));
    }
}

// ---------------- HMMA tf32 GEMM (unchanged — proven) ----------------
#define NKT (CC/32)   // 12

template<int MODE>
__global__ void __launch_bounds__(128)
tgemm_tc(const float* __restrict__ aux, float* __restrict__ out) {
    __shared__ __align__(128) char smem[2 * 24576];   // 48KB static
    const uint32_t sbase = smem_u32(smem);
    const int tid  = threadIdx.x;
    const int lane = tid & 31;
    const int warp = tid >> 5;
    const int wm   = warp >> 1;
    const int wn   = warp & 1;
    const int row0 = blockIdx.y * 128;
    const int col0 = blockIdx.x * 64;

    const float* Ap = (MODE == 2) ? (const float*)g_q : (const float*)g_xtf;
    const float* Bt = (MODE == 0) ? (const float*)g_Wt_qg
                    : (MODE == 1) ? (const float*)g_Wt_kv
                                  : (const float*)g_Wt_pj;

    float acc[4][4][4];
#pragma unroll
    for (int i = 0; i < 4; i++)
#pragma unroll
        for (int j = 0; j < 4; j++)
#pragma unroll
            for (int f = 0; f < 4; f++) acc[i][j][f] = 0.0f;

    const int lm = lane >> 3;
    const int lr = lane & 7;
    const int rowA = wm * 64 + (lm & 1) * 8 + lr;
    const unsigned kgA = (lm >> 1) * 16;
    const unsigned XA  = (rowA & 7) << 4;
    const int rowB = wn * 32 + (lm >> 1) * 8 + lr;
    const unsigned kgB = (lm & 1) * 16;
    const unsigned XB  = (rowB & 7) << 4;

    auto load_tile = [&](int kt, int s) {
        const int kb = kt * 32;
        const uint32_t dA = sbase + s * 24576;
        const uint32_t dB = dA + 16384;
#pragma unroll
        for (int i = 0; i < 8; i++) {
            int c = tid + i * 128;
            int r = c >> 3, kq = c & 7;
            unsigned off = r * 128 + kq * 16;
            off ^= (off >> 3) & 0x70;
            cp16(dA + off, Ap + (size_t)(row0 + r) * CC + kb + kq * 4);
        }
#pragma unroll
        for (int i = 0; i < 4; i++) {
            int c = tid + i * 128;
            int r = c >> 3, kq = c & 7;
            unsigned off = r * 128 + kq * 16;
            off ^= (off >> 3) & 0x70;
            cp16(dB + off, Bt + (size_t)(col0 + r) * CC + kb + kq * 4);
        }
        CP_COMMIT();
    };

    auto compute_stage = [&](int s) {
        const uint32_t bA = sbase + s * 24576;
        const uint32_t bB = bA + 16384;
#pragma unroll
        for (int ks = 0; ks < 4; ks++) {
            uint32_t af[4][4], bf[2][4];
            const unsigned colA = (unsigned)(ks * 32 + kgA) ^ XA;
            const unsigned colB = (unsigned)(ks * 32 + kgB) ^ XB;
#pragma unroll
            for (int mi = 0; mi < 4; mi++)
                ldsm4(af[mi], bA + (rowA + mi * 16) * 128 + colA);
#pragma unroll
            for (int np = 0; np < 2; np++)
                ldsm4(bf[np], bB + (rowB + np * 16) * 128 + colB);
#pragma unroll
            for (int mi = 0; mi < 4; mi++)
#pragma unroll
                for (int np = 0; np < 2; np++) {
                    mma_tf32(acc[mi][2 * np],     af[mi], bf[np][0], bf[np][1]);
                    mma_tf32(acc[mi][2 * np + 1], af[mi], bf[np][2], bf[np][3]);
                }
        }
    };

    load_tile(0, 0);
    load_tile(1, 1);

    for (int c = 0; c < NKT - 1; c++) {
        CP_WAIT1();
        __syncthreads();
        compute_stage(c & 1);
        __syncthreads();
        if (c + 2 < NKT) load_tile(c + 2, c & 1);
    }
    CP_WAIT0();
    __syncthreads();
    compute_stage((NKT - 1) & 1);

    const int gq = lane >> 2;
    const int c2 = (lane & 3) * 2;
    const bool qhalf = (col0 < CC);
#pragma unroll
    for (int mi = 0; mi < 4; mi++) {
        const int rb = row0 + wm * 64 + mi * 16 + gq;
#pragma unroll
        for (int ni = 0; ni < 4; ni++) {
            const int col = col0 + wn * 32 + ni * 8 + c2;
#pragma unroll
            for (int h = 0; h < 2; h++) {
                const int r = rb + h * 8;
                float v0 = acc[mi][ni][h * 2];
                float v1 = acc[mi][ni][h * 2 + 1];
                if (MODE == 0) {
                    if (qhalf) {
                        float2 s = *(const float2*)&g_scale[col];
                        *(float2*)&g_q[(size_t)r * CC + col] = make_float2(v0 / s.x, v1 / s.y);
                    } else {
                        *(float2*)&g_g[(size_t)r * CC + (col - CC)] = make_float2(v0, v1);
                    }
                } else if (MODE == 1) {
                    if (qhalf) {
                        int n = r & (NN - 1);
                        float2 pe = *(const float2*)&aux[(size_t)n * CC + col];
                        float2 s  = *(const float2*)&g_scale[col];
                        *(float2*)&g_k[(size_t)r * CC + col] =
                            make_float2((v0 + pe.x) / s.x, (v1 + pe.y) / s.y);
                    } else {
                        *(float2*)&g_v[(size_t)r * CC + (col - CC)] = make_float2(v0, v1);
                    }
                } else {
                    float2 bb = *(const float2*)&aux[col];
                    *(float2*)&out[(size_t)r * CC + col] = make_float2(v0 + bb.x, v1 + bb.y);
                }
            }
        }
    }
}

// ---------------- reduction: KV[bh][u][e] and km[bh][u] (one powf per element) ----------------
// grid (BH, 32 chunks of 512 tokens), 256 threads; batches of 32 tokens.
__global__ void __launch_bounds__(256) reduce_kv_kernel() {
    int bh = blockIdx.x;
    int b = bh >> 3, h = bh & 7;
    int chunk = blockIdx.y;
    int t = threadIdx.x;

    __shared__ float s_kraw[32][49];   // raw k batch (odd pad: conflict-free col reads)
    __shared__ float s_vT[48][36];     // v transposed (rows 144B, 16B-aligned)
    __shared__ float s_kkT[96][36];    // features transposed

    const int tok_l = t & 31;          // feature-phase token
    const int ubase = t >> 5;          // warp id: all lanes share the d-set
    float pw[6];
#pragma unroll
    for (int j = 0; j < 6; j++) {
        int d = ubase + 8 * j;
        pw[j] = g_power[h * 48 + d];
    }
    float kmacc[12];
#pragma unroll
    for (int j = 0; j < 12; j++) kmacc[j] = 0.0f;

    const int ug = t >> 4, eg = t & 15;
    const int u0 = ug * 6, e0 = eg * 3;
    float acc[6][3];
#pragma unroll
    for (int i = 0; i < 6; i++)
#pragma unroll
        for (int j = 0; j < 3; j++) acc[i][j] = 0.0f;

    size_t base = ((size_t)(b * NN) + (size_t)chunk * 512) * CC + h * 48;

    for (int batch = 0; batch < 16; batch++) {
        // load 32 tokens of k (row-major) and v (transposed), coalesced gmem reads
#pragma unroll
        for (int i = 0; i < 6; i++) {
            int e = t + i * 256;       // < 1536
            int tok = e / 48, dd = e % 48;
            size_t gi = base + (size_t)(batch * 32 + tok) * CC + dd;
            s_kraw[tok][dd] = g_k[gi];
            s_vT[dd][tok]   = g_v[gi];
        }
        __syncthreads();

        // features: ONE powf per (token, d); route by sign into d / d+48
#pragma unroll
        for (int j = 0; j < 6; j++) {
            int d = ubase + 8 * j;
            float kv = s_kraw[tok_l][d];
            float av = fabsf(kv);
            float val = (av > 0.0f) ? __powf(av, pw[j]) : 0.0f;
            float vp = (kv > 0.0f) ? val : 0.0f;
            float vn = (kv < 0.0f) ? val : 0.0f;
            s_kkT[d][tok_l]      = vp;
            s_kkT[d + 48][tok_l] = vn;
            kmacc[j]     += vp;       // u = d        = ubase + 8*j
            kmacc[j + 6] += vn;       // u = d + 48   = ubase + 8*(j+6)
        }
        __syncthreads();

        // accumulate: float4 over tokens, 72 FMA per 9 LDS.128
#pragma unroll
        for (int tc = 0; tc < 32; tc += 4) {
            float4 kk[6], vv[3];
#pragma unroll
            for (int i = 0; i < 6; i++) kk[i] = *(const float4*)&s_kkT[u0 + i][tc];
#pragma unroll
            for (int j = 0; j < 3; j++) vv[j] = *(const float4*)&s_vT[e0 + j][tc];
#pragma unroll
            for (int i = 0; i < 6; i++) {
                const float* kf = (const float*)&kk[i];
#pragma unroll
                for (int j = 0; j < 3; j++) {
                    const float* vf = (const float*)&vv[j];
                    acc[i][j] = fmaf(kf[0], vf[0], acc[i][j]);
                    acc[i][j] = fmaf(kf[1], vf[1], acc[i][j]);
                    acc[i][j] = fmaf(kf[2], vf[2], acc[i][j]);
                    acc[i][j] = fmaf(kf[3], vf[3], acc[i][j]);
                }
            }
        }
        __syncthreads();
    }

#pragma unroll
    for (int i = 0; i < 6; i++)
#pragma unroll
        for (int j = 0; j < 3; j++)
            atomicAdd(&g_KV[((size_t)bh * FF + u0 + i) * HD + e0 + j], acc[i][j]);

    // km: warp-reduce (all lanes share u-set), lane 0 commits
#pragma unroll
    for (int j = 0; j < 12; j++) {
        float v = kmacc[j];
#pragma unroll
        for (int off = 16; off > 0; off >>= 1)
            v += __shfl_xor_sync(0xFFFFFFFFu, v, off);
        if ((t & 31) == 0)
            atomicAdd(&g_km[(size_t)bh * FF + ubase + 8 * j], v);
    }
}

// ---------------- per-token attention (one powf per element) ----------------
// grid (NN/64, BH), 256 threads; 64 tokens per block
__global__ void __launch_bounds__(256) attn_kernel() {
    int bh = blockIdx.y;
    int b = bh >> 3, h = bh & 7;
    int n0 = blockIdx.x * 64;
    int t = threadIdx.x;

    __shared__ float s_qsT[96][68];    // features transposed (272B rows, 16B-aligned)
    __shared__ float s_MT[48][100];    // M transposed [e][u] (400B rows, 16B-aligned)
    __shared__ float s_km[96];
    __shared__ float s_z[64][2];

    float (*s_qraw)[49] = (float(*)[49])&s_MT[0][0];   // 64*49 = 3136 <= 4800 floats

    size_t base = ((size_t)(b * NN) + n0) * CC + h * 48;

    // phase 1: raw q tile (odd-padded rows) + km
    for (int e = t; e < 64 * 48; e += 256) {
        int tok = e / 48, d = e % 48;
        s_qraw[tok][d] = g_q[base + (size_t)tok * CC + d];
    }
    if (t < 96) s_km[t] = g_km[(size_t)bh * FF + t] * INV_N;
    __syncthreads();

    // phase 2: ONE powf per (token, d); route by sign into slots d / d+48
    for (int idx = t; idx < 48 * 64; idx += 256) {
        int d = idx >> 6, tok = idx & 63;
        float qv = s_qraw[tok][d];
        float av = fabsf(qv);
        float p = g_power[h * 48 + d];
        float pv = (av > 0.0f) ? __powf(av, p) : 0.0f;
        s_qsT[d][tok]      = (qv > 0.0f) ? pv : 0.0f;
        s_qsT[d + 48][tok] = (qv < 0.0f) ? pv : 0.0f;
    }
    __syncthreads();

    // phase 3: z per token (2 threads/token + shfl) + M load (overwrites s_qraw alias)
    if (t < 128) {
        int tok = t >> 1, uh = (t & 1) * 48;
        float zs = 0.0f, zo = 0.0f;
#pragma unroll
        for (int uu = 0; uu < 48; uu++) {
            int u = uh + uu;
            float qv = s_qsT[u][tok];
            zs = fmaf(qv, s_km[u], zs);
            zo = fmaf(qv, s_km[(u + 48) % 96], zo);
        }
        zs += __shfl_xor_sync(0xFFFFFFFFu, zs, 1);
        zo += __shfl_xor_sync(0xFFFFFFFFu, zo, 1);
        if ((t & 1) == 0) {
            s_z[tok][0] = 1.0f / (zs + 1e-6f);
            s_z[tok][1] = 1.0f / (zo + 1e-6f);
        }
    }
    for (int idx = t; idx < 48 * 96; idx += 256) {
        int e = idx / 96, u = idx % 96;
        int usrc = (e < 24) ? u : ((u + 48) % 96);
        s_MT[e][u] = g_KV[((size_t)bh * FF + usrc) * HD + e] * INV_N;
    }
    __syncthreads();

    // phase 4: out[64][48] = qsT^T @ MT^T via float4 chunks over u
    const int tg = t >> 4, eg = t & 15;
    const int tok0 = tg * 4, e0 = eg * 3;
    float acc[4][3];
#pragma unroll
    for (int i = 0; i < 4; i++)
#pragma unroll
        for (int j = 0; j < 3; j++) acc[i][j] = 0.0f;

#pragma unroll 4
    for (int k = 0; k < 96; k += 4) {
        float4 qa[4], mb[3];
#pragma unroll
        for (int kk2 = 0; kk2 < 4; kk2++) qa[kk2] = *(const float4*)&s_qsT[k + kk2][tok0];
#pragma unroll
        for (int j = 0; j < 3; j++) mb[j] = *(const float4*)&s_MT[e0 + j][k];
#pragma unroll
        for (int kk2 = 0; kk2 < 4; kk2++) {
            const float* qf = (const float*)&qa[kk2];
#pragma unroll
            for (int j = 0; j < 3; j++) {
                const float* mf = (const float*)&mb[j];
                float mv = mf[kk2];
                acc[0][j] = fmaf(qf[0], mv, acc[0][j]);
                acc[1][j] = fmaf(qf[1], mv, acc[1][j]);
                acc[2][j] = fmaf(qf[2], mv, acc[2][j]);
                acc[3][j] = fmaf(qf[3], mv, acc[3][j]);
            }
        }
    }

#pragma unroll
    for (int i = 0; i < 4; i++) {
        int tok = tok0 + i;
#pragma unroll
        for (int j = 0; j < 3; j++) {
            int e = e0 + j;
            float z = s_z[tok][(e < 24) ? 0 : 1];
            g_attn[base + (size_t)tok * CC + e] = acc[i][j] * z;
        }
    }
}

// ---------------- depthwise conv + combine, float4 channels ----------------
__global__ void __launch_bounds__(256) conv_combine_kernel(const float* __restrict__ w,
                                                           const float* __restrict__ wb) {
    __shared__ float s_w4[25][48];     // [tap][d]
    __shared__ float s_b[48];
    int t = threadIdx.x;
    for (int i = t; i < 25 * 48; i += 256) {
        int tap = i % 25, d = i / 25;
        s_w4[tap][d] = w[d * 25 + tap];
    }
    if (t < 48) s_b[t] = wb[t];
    __syncthreads();

    int idx = blockIdx.x * 256 + t;            // element-quad index < 6,291,456
    int c4 = idx % 96;                          // CC/4
    int rown = idx / 96;                        // b*N + n
    int c = c4 * 4;
    int n = rown & (NN - 1);
    int b = rown >> 14;
    int d = c % 48;                             // 4 | 48 -> d..d+3 same head
    int y = n >> 7, x = n & 127;

    float4 bv = *(const float4*)&s_b[d];
    float a0 = bv.x, a1 = bv.y, a2 = bv.z, a3 = bv.w;
#pragma unroll
    for (int dy = -2; dy <= 2; dy++) {
        int yy = y + dy;
        if ((unsigned)yy < 128u) {
#pragma unroll
            for (int dx = -2; dx <= 2; dx++) {
                int xx = x + dx;
                if ((unsigned)xx < 128u) {
                    int tap = (dy + 2) * 5 + (dx + 2);
                    float4 vv = *(const float4*)&g_v[((size_t)(b << 14) + (yy << 7) + xx) * CC + c];
                    float4 ww = *(const float4*)&s_w4[tap][d];
                    a0 = fmaf(vv.x, ww.x, a0);
                    a1 = fmaf(vv.y, ww.y, a1);
                    a2 = fmaf(vv.z, ww.z, a2);
                    a3 = fmaf(vv.w, ww.w, a3);
                }
            }
        }
    }
    size_t gi = (size_t)idx * 4;               // == rown*CC + c
    float4 at = *(const float4*)&g_attn[gi];
    float4 gg = *(const float4*)&g_g[gi];
    uint4 o;
    o.x = f2tf((at.x + a0) * gg.x);
    o.y = f2tf((at.y + a1) * gg.y);
    o.z = f2tf((at.z + a2) * gg.z);
    o.w = f2tf((at.w + a3) * gg.w);
    *(uint4*)&g_q[gi] = o;                     // tf32-rounded "pre" for proj GEMM
}

// ---------------- launch (kernel launches ONLY) ----------------
extern "C" void kernel_launch(void* const* d_in, const int* in_sizes, int n_in,
                              void* d_out, int out_size) {
    const float* x       = (const float*)d_in[0];
    const float* W_qg    = (const float*)d_in[1];
    const float* W_kv    = (const float*)d_in[2];
    const float* W_proj  = (const float*)d_in[3];
    const float* b_proj  = (const float*)d_in[4];
    const float* pos_enc = (const float*)d_in[5];
    const float* power_p = (const float*)d_in[6];
    const float* scale_p = (const float*)d_in[7];
    const float* dwc_w   = (const float*)d_in[8];
    const float* dwc_b   = (const float*)d_in[9];
    float* out = (float*)d_out;

    prep_kernel<<<1, 384>>>(scale_p, power_p);
    zero_kv_kernel<<<(BH * FF * HD + 255) / 256, 256>>>();
    round_x_kernel<<<(ROWS * CC) / 1024, 256>>>(x);

    transpose_cvt_kernel<0><<<dim3(768 / 32, 384 / 32), dim3(32, 8)>>>(W_qg, 384, 768);
    transpose_cvt_kernel<1><<<dim3(768 / 32, 384 / 32), dim3(32, 8)>>>(W_kv, 384, 768);
    transpose_cvt_kernel<2><<<dim3(384 / 32, 384 / 32), dim3(32, 8)>>>(W_proj, 384, 384);

    tgemm_tc<0><<<dim3(12, ROWS / 128), 128>>>(nullptr, nullptr);
    tgemm_tc<1><<<dim3(12, ROWS / 128), 128>>>(pos_enc, nullptr);

    reduce_kv_kernel<<<dim3(BH, 32), 256>>>();
    attn_kernel<<<dim3(NN / 64, BH), 256>>>();
    conv_combine_kernel<<<(ROWS * CC / 4) / 256, 256>>>(dwc_w, dwc_b);

    tgemm_tc<2><<<dim3(6, ROWS / 128), 128>>>(b_proj, out);
}